// round 12
// baseline (speedup 1.0000x reference)
#include <cuda_runtime.h>
#include <cuda_fp16.h>
#include <math.h>
#include <stdint.h>

#define B_   4
#define NPIX 16384
#define OMC  216
#define KDCN 2304

// ---------------- scratch (device globals) -----------------------------------
__device__ float g_part[32*B_*256];
__device__ float g_scale[B_*256];
__device__ float g_fine_cal[NPIX*256];
__device__ float g_om[NPIX*OMC];

__device__ __half g_fs_h[NPIX*256];                  // mode0 A (fp16)
__device__ __half g_cat_hi[NPIX*512];                // mode2 A (fp16); cols 256.. = 2*coarse_up
__device__ __half g_cols_hi[(size_t)NPIX*KDCN];      // mode3 A (fp16)

// weights
__device__ __half g_bt0h[256*256];                   // fs_conv_w^T fp16
__device__ __half g_bt2h[256*4608];                  // Wcomb^T fp16 (pad n 216->256)
__device__ __half g_bt3h[256*2304];                  // dcn_kernel^T fp16
__device__ __half g_ow_h[512*512], g_ow_l[512*512];  // offset_w split [c][f]
__device__ __half g_omt[9*256*512];                  // om_w^T fp16 [tap][n(pad)][f]

// ---------------- helpers ------------------------------------------------------
static __device__ __forceinline__ uint32_t smem_u32(const void* p){
    uint32_t a;
    asm("{ .reg .u64 t; cvta.to.shared.u64 t, %1; cvt.u32.u64 %0, t; }" : "=r"(a) : "l"(p));
    return a;
}
static __device__ __forceinline__ void cpa16(uint32_t dst, const void* src, int pbytes){
    asm volatile("cp.async.ca.shared.global [%0], [%1], 16, %2;"
                 :: "r"(dst), "l"(src), "r"(pbytes));
}
#define CP_COMMIT  asm volatile("cp.async.commit_group;" ::: "memory")
#define CP_WAIT1   asm volatile("cp.async.wait_group 1;" ::: "memory")
#define CP_WAIT0   asm volatile("cp.async.wait_group 0;" ::: "memory")
#define LDSM_X4(r, a) \
    asm volatile("ldmatrix.sync.aligned.m8n8.x4.shared.b16 {%0,%1,%2,%3}, [%4];" \
        : "=r"((r)[0]),"=r"((r)[1]),"=r"((r)[2]),"=r"((r)[3]) : "r"(a))
#define MMA16816(d, a, b0, b1) \
    asm volatile("mma.sync.aligned.m16n8k16.row.col.f32.f16.f16.f32 " \
        "{%0,%1,%2,%3}, {%4,%5,%6,%7}, {%8,%9}, {%0,%1,%2,%3};" \
        : "+f"((d)[0]),"+f"((d)[1]),"+f"((d)[2]),"+f"((d)[3]) \
        : "r"((a)[0]),"r"((a)[1]),"r"((a)[2]),"r"((a)[3]), "r"(b0), "r"(b1))

static __device__ __forceinline__ void split2(float v, __half& h, __half& l){
    h = __float2half_rn(v);
    l = __float2half_rn(v - __half2float(h));
}
static __device__ __forceinline__ uint32_t packh2(float x, float y){
    __half hx = __float2half_rn(x), hy = __float2half_rn(y);
    return (uint32_t)__half_as_ushort(hx) | ((uint32_t)__half_as_ushort(hy) << 16);
}

// ---------------- prep kernels ---------------------------------------------------
__global__ void gap_partial(const float* __restrict__ fine){
    int blk = blockIdx.x, b = blk >> 5, chunk = blk & 31, c = threadIdx.x;
    const float* p = fine + ((size_t)(b*4096 + chunk*128))*256 + c;
    float s = 0.f;
    #pragma unroll 8
    for (int r = 0; r < 128; r++) s += p[(size_t)r*256];
    g_part[blk*256 + c] = s;
}
__global__ void attn_kernel(const float* __restrict__ W){
    __shared__ float gp[256];
    int b = blockIdx.x, t = threadIdx.x;
    float s = 0.f;
    #pragma unroll
    for (int ch = 0; ch < 32; ch++) s += g_part[(b*32 + ch)*256 + t];
    gp[t] = s * (1.f/4096.f);
    __syncthreads();
    float acc = 0.f;
    for (int c = 0; c < 256; c++) acc += gp[c] * W[c*256 + t];
    g_scale[b*256 + t] = 1.f + 1.f/(1.f + expf(-acc));
}
// upsample(->cat coarse half) + fine*scale fp16 prep; 4 channels/thread, float4
__global__ void prep_pix(const float* __restrict__ fine, const float* __restrict__ coarse){
    int t = threadIdx.x;
    int m = blockIdx.x*4 + (t >> 6);
    int c = (t & 63)*4;
    int b = m >> 12, rem = m & 4095, y = rem >> 6, x = rem & 63;
    float fy = 0.5f*y - 0.25f, fx = 0.5f*x - 0.25f;
    float y0f = floorf(fy), x0f = floorf(fx);
    float wy1 = fy - y0f, wx1 = fx - x0f, wy0 = 1.f - wy1, wx0 = 1.f - wx1;
    int y0 = (int)y0f, x0 = (int)x0f;
    int y0c = min(max(y0,0),31), y1c = min(max(y0+1,0),31);
    int x0c = min(max(x0,0),31), x1c = min(max(x0+1,0),31);
    const float* cb = coarse + (size_t)(b*1024)*256 + c;
    float4 v00 = *(const float4*)(cb + (size_t)(y0c*32+x0c)*256);
    float4 v01 = *(const float4*)(cb + (size_t)(y0c*32+x1c)*256);
    float4 v10 = *(const float4*)(cb + (size_t)(y1c*32+x0c)*256);
    float4 v11 = *(const float4*)(cb + (size_t)(y1c*32+x1c)*256);
    float w00 = wy0*wx0, w01 = wy0*wx1, w10 = wy1*wx0, w11 = wy1*wx1;
    float4 v;
    v.x = w00*v00.x + w01*v01.x + w10*v10.x + w11*v11.x;
    v.y = w00*v00.y + w01*v01.y + w10*v10.y + w11*v11.y;
    v.z = w00*v00.z + w01*v01.z + w10*v10.z + w11*v11.z;
    v.w = w00*v00.w + w01*v01.w + w10*v10.w + w11*v11.w;
    uint2 co;
    co.x = packh2(2.f*v.x, 2.f*v.y);
    co.y = packh2(2.f*v.z, 2.f*v.w);
    *(uint2*)(g_cat_hi + (size_t)m*512 + 256 + c) = co;
    float4 f4 = *(const float4*)(fine + (size_t)m*256 + c);
    float4 s4 = *(const float4*)(g_scale + b*256 + c);
    uint2 fo;
    fo.x = packh2(f4.x*s4.x, f4.y*s4.y);
    fo.y = packh2(f4.z*s4.z, f4.w*s4.w);
    *(uint2*)(g_fs_h + (size_t)m*256 + c) = fo;
}

// ---- unified weight prep: one launch, blockIdx-range dispatch --------------------
__global__ void wprep(const float* __restrict__ fs_conv_w,
                      const float* __restrict__ dcn_w,
                      const float* __restrict__ offw,
                      const float* __restrict__ omw){
    __shared__ float tile[32][33];
    int blk = blockIdx.x;
    if (blk < 640){
        const float* W = (blk < 64) ? fs_conv_w : dcn_w;
        __half* T      = (blk < 64) ? g_bt0h    : g_bt3h;
        int KROWS      = (blk < 64) ? 256       : 2304;
        int b = (blk < 64) ? blk : blk - 64;
        int k0 = (b >> 3)*32, n0 = (b & 7)*32;
        int tx = threadIdx.x & 31, ty = threadIdx.x >> 5;
        #pragma unroll
        for (int i = 0; i < 4; i++)
            tile[ty + i*8][tx] = W[(size_t)(k0 + ty + i*8)*256 + n0 + tx];
        __syncthreads();
        #pragma unroll
        for (int i = 0; i < 4; i++)
            T[(size_t)(n0 + ty + i*8)*KROWS + k0 + tx] = __float2half_rn(tile[tx][ty + i*8]);
    } else if (blk < 1664){
        int i = (blk - 640)*256 + threadIdx.x;
        __half h, l; split2(offw[i], h, l);
        g_ow_h[i] = h; g_ow_l[i] = l;
    } else {
        int b = blk - 1664;
        int f = (b & 1)*256 + threadIdx.x;
        int n = (b >> 1) % 216;
        int tap = b / 432;
        g_omt[((size_t)tap*256 + n)*512 + f] =
            __float2half_rn(omw[((size_t)tap*512 + f)*216 + n]);
    }
}

// ---- Wcomb via HMMA (2-term: A hi/lo, B fp16) -----------------------------------
__global__ void __launch_bounds__(256)
wcomb_mma(){
    constexpr int Kk = 512, NC = 8;
    extern __shared__ __align__(16) char smem[];
    uint32_t sb = smem_u32(smem);
    int tid = threadIdx.x, lane = tid & 31, wid = tid >> 5;
    int m0 = blockIdx.x*128, n0 = blockIdx.y*128, tap = blockIdx.z;
    int wm = wid >> 2, wn = wid & 3;
    const __half* Bh = g_omt + (size_t)tap*256*512;

    auto load_chunk = [&](int stage, int k0){
        uint32_t base = sb + stage*49152;
        #pragma unroll
        for (int u = 0; u < 4; u++){
            int idx = tid + u*256;
            int row = idx >> 3, ch = idx & 7;
            uint32_t d = base + (uint32_t)(row*128 + ((ch ^ (row & 7)) << 4));
            size_t aoff = (size_t)(m0 + row)*Kk + k0 + ch*8;
            size_t boff = (size_t)(n0 + row)*Kk + k0 + ch*8;
            cpa16(d,         g_ow_h + aoff, 16);
            cpa16(d + 16384, g_ow_l + aoff, 16);
            cpa16(d + 32768, Bh + boff, 16);
        }
    };

    int rbase = wm*64 + ((lane >> 3) & 1)*8 + (lane & 7);
    int khA   = lane >> 4;
    int nbase = wn*32 + ((lane >> 4) & 1)*8 + (lane & 7);
    int khB   = (lane >> 3) & 1;
    uint32_t aswz = (uint32_t)(rbase & 7), bswz = (uint32_t)(nbase & 7);

    float acc[4][4][4];
    #pragma unroll
    for (int i = 0; i < 4; i++)
        #pragma unroll
        for (int j = 0; j < 4; j++)
            #pragma unroll
            for (int q = 0; q < 4; q++) acc[i][j][q] = 0.f;

    load_chunk(0, 0);
    CP_COMMIT;
    for (int c = 0; c < NC; c++){
        if (c + 1 < NC) load_chunk((c + 1) & 1, (c + 1)*64);
        CP_COMMIT;
        if (c + 1 < NC) CP_WAIT1; else CP_WAIT0;
        __syncthreads();
        uint32_t base = sb + (c & 1)*49152;
        #pragma unroll
        for (int ks = 0; ks < 4; ks++){
            uint32_t aH[4][4], aL[4][4], bH[2][4];
            #pragma unroll
            for (int mi = 0; mi < 4; mi++){
                uint32_t off = base + (uint32_t)((rbase + mi*16)*128
                             + ((((uint32_t)(ks*2 + khA)) ^ aswz) << 4));
                LDSM_X4(aH[mi], off);
                LDSM_X4(aL[mi], off + 16384);
            }
            #pragma unroll
            for (int nb = 0; nb < 2; nb++){
                uint32_t off = base + 32768 + (uint32_t)((nbase + nb*16)*128
                             + ((((uint32_t)(ks*2 + khB)) ^ bswz) << 4));
                LDSM_X4(bH[nb], off);
            }
            #pragma unroll
            for (int mi = 0; mi < 4; mi++)
                #pragma unroll
                for (int nj = 0; nj < 4; nj++){
                    uint32_t h0 = bH[nj >> 1][(nj & 1)*2], h1 = bH[nj >> 1][(nj & 1)*2 + 1];
                    MMA16816(acc[mi][nj], aH[mi], h0, h1);
                    MMA16816(acc[mi][nj], aL[mi], h0, h1);
                }
        }
        __syncthreads();
    }

    int g = lane >> 2, th = lane & 3;
    #pragma unroll
    for (int mi = 0; mi < 4; mi++){
        #pragma unroll
        for (int nj = 0; nj < 4; nj++){
            int col = n0 + wn*32 + nj*8 + th*2;
            float* a = acc[mi][nj];
            #pragma unroll
            for (int half = 0; half < 2; half++){
                int m = m0 + wm*64 + mi*16 + g + half*8;
                if (col < OMC){
                    g_bt2h[(size_t)col*4608 + tap*512 + m]     = __float2half_rn(a[half*2]);
                    g_bt2h[(size_t)(col+1)*4608 + tap*512 + m] = __float2half_rn(a[half*2+1]);
                }
            }
        }
    }
}

// ------- warp-MMA GEMM, 1-term fp16, BM128 BN256 BK64, 512 threads --------------
// A read once per m-block (no n-split). 16 warps: 4x4 grid, warp tile 32x64.
// MODE 0: fine_cal = fs_h @ bt0                (K=256)
// MODE 2: om = im2col(cat_hi) @ bt2 + bias      (K=4608, n<216)
// MODE 3: out = relu(cols_hi @ bt3 + b) + fc    (K=2304)
template<int MODE>
__global__ void __launch_bounds__(512)
mmagemm(const float* __restrict__ bias, float* __restrict__ outp){
    constexpr int Kk = (MODE==0) ? 256 : (MODE==2) ? 4608 : 2304;
    constexpr int NC = Kk / 64;
    constexpr uint32_t STAGE = 49152;      // A 16KB + B 32KB
    const __half* Ah = (MODE==0) ? g_fs_h : (MODE==2) ? g_cat_hi : g_cols_hi;
    const __half* Bh = (MODE==0) ? g_bt0h : (MODE==2) ? g_bt2h : g_bt3h;

    extern __shared__ __align__(16) char smem[];
    uint32_t sb = smem_u32(smem);
    int tid = threadIdx.x, lane = tid & 31, wid = tid >> 5;
    int m0 = blockIdx.x*128;
    int wm = wid >> 2, wn = wid & 3;

    auto load_chunk = [&](int stage, int k0){
        uint32_t base = sb + stage*STAGE;
        // B: 256 rows x 8 x 16B = 2048 ops
        #pragma unroll
        for (int u = 0; u < 4; u++){
            int idx = tid + u*512;
            int row = idx >> 3, ch = idx & 7;
            uint32_t d = base + 16384 + (uint32_t)(row*128 + ((ch ^ (row & 7)) << 4));
            cpa16(d, Bh + (size_t)row*Kk + k0 + ch*8, 16);
        }
        // A: 128 rows x 8 x 16B = 1024 ops
        #pragma unroll
        for (int u = 0; u < 2; u++){
            int idx = tid + u*512;
            int row = idx >> 3, ch = idx & 7;
            uint32_t d = base + (uint32_t)(row*128 + ((ch ^ (row & 7)) << 4));
            if (MODE == 2){
                int m = m0 + row, bb = m >> 12, rem = m & 4095;
                int yy = rem >> 6, xx = rem & 63;
                int tap = k0 >> 9, cc = (k0 & 511) + ch*8;
                int ny = yy + tap/3 - 1, nx = xx + tap%3 - 1;
                bool ok = ((unsigned)ny < 64u) && ((unsigned)nx < 64u);
                size_t aoff = ok ? ((size_t)((bb << 12) + ny*64 + nx)*512 + cc) : 0;
                cpa16(d, Ah + aoff, ok ? 16 : 0);
            } else {
                cpa16(d, Ah + (size_t)(m0 + row)*Kk + k0 + ch*8, 16);
            }
        }
    };

    int rbase = wm*32 + ((lane >> 3) & 1)*8 + (lane & 7);
    int khA   = lane >> 4;
    int nbase = wn*64 + ((lane >> 4) & 1)*8 + (lane & 7);
    int khB   = (lane >> 3) & 1;
    uint32_t aswz = (uint32_t)(rbase & 7), bswz = (uint32_t)(nbase & 7);

    float acc[2][8][4];
    #pragma unroll
    for (int i = 0; i < 2; i++)
        #pragma unroll
        for (int j = 0; j < 8; j++)
            #pragma unroll
            for (int q = 0; q < 4; q++) acc[i][j][q] = 0.f;

    load_chunk(0, 0);
    CP_COMMIT;
    for (int c = 0; c < NC; c++){
        if (c + 1 < NC) load_chunk((c + 1) & 1, (c + 1)*64);
        CP_COMMIT;
        if (c + 1 < NC) CP_WAIT1; else CP_WAIT0;
        __syncthreads();
        uint32_t base = sb + (c & 1)*STAGE;
        #pragma unroll
        for (int ks = 0; ks < 4; ks++){
            uint32_t aH[2][4], bH[4][4];
            #pragma unroll
            for (int mi = 0; mi < 2; mi++){
                uint32_t off = base + (uint32_t)((rbase + mi*16)*128
                             + ((((uint32_t)(ks*2 + khA)) ^ aswz) << 4));
                LDSM_X4(aH[mi], off);
            }
            #pragma unroll
            for (int nb = 0; nb < 4; nb++){
                uint32_t off = base + 16384 + (uint32_t)((nbase + nb*16)*128
                             + ((((uint32_t)(ks*2 + khB)) ^ bswz) << 4));
                LDSM_X4(bH[nb], off);
            }
            #pragma unroll
            for (int mi = 0; mi < 2; mi++)
                #pragma unroll
                for (int nj = 0; nj < 8; nj++){
                    uint32_t h0 = bH[nj >> 1][(nj & 1)*2], h1 = bH[nj >> 1][(nj & 1)*2 + 1];
                    MMA16816(acc[mi][nj], aH[mi], h0, h1);
                }
        }
        __syncthreads();
    }

    int g = lane >> 2, th = lane & 3;
    #pragma unroll
    for (int mi = 0; mi < 2; mi++){
        #pragma unroll
        for (int nj = 0; nj < 8; nj++){
            int col = wn*64 + nj*8 + th*2;
            float* a = acc[mi][nj];
            #pragma unroll
            for (int half = 0; half < 2; half++){
                int m = m0 + wm*32 + mi*16 + g + half*8;
                float x = a[half*2], y = a[half*2 + 1];
                if (MODE == 0){
                    *(float2*)(g_fine_cal + (size_t)m*256 + col) = make_float2(x, y);
                    *(uint32_t*)(g_cat_hi + (size_t)m*512 + col) = packh2(x, y);
                } else if (MODE == 2){
                    if (col < OMC)
                        *(float2*)(g_om + (size_t)m*OMC + col) =
                            make_float2(x + bias[col], y + bias[col + 1]);
                } else {
                    float2 fc = *(const float2*)(g_fine_cal + (size_t)m*256 + col);
                    float2 o;
                    o.x = fmaxf(x + bias[col],     0.f) + fc.x;
                    o.y = fmaxf(y + bias[col + 1], 0.f) + fc.y;
                    *(float2*)(outp + (size_t)m*256 + col) = o;
                }
            }
        }
    }
}

// -------- deformable sampling: 1 warp = 1 pixel, uint2 gathers from cat_hi -------
__global__ __launch_bounds__(256)
void dcn_sample(){
    __shared__ float oms[8*OMC];
    int tid = threadIdx.x;
    int pixBase = blockIdx.x * 8;
    for (int i = tid; i < 8*OMC; i += 256)
        oms[i] = g_om[(size_t)pixBase*OMC + i];
    __syncthreads();

    int wid = tid >> 5, lane = tid & 31;
    int g4 = lane >> 3, l8 = lane & 7;
    int m = pixBase + wid;
    int b = m >> 12, rem = m & 4095, y = rem >> 6, x = rem & 63;
    const float* om = oms + wid*OMC;
    __half* colB = g_cols_hi + (size_t)m*KDCN;

    #pragma unroll
    for (int t = 0; t < 9; t++){
        int tyo = t/3 - 1, txo = t - (t/3)*3 - 1;
        #pragma unroll
        for (int gp = 0; gp < 2; gp++){
            int g = gp*4 + g4;
            float dy = om[g*18 + t*2];
            float dx = om[g*18 + t*2 + 1];
            float mk = 1.f / (1.f + __expf(-om[144 + g*9 + t]));  // (2*sig)*0.5
            float py = (float)(y + tyo) + dy;
            float px = (float)(x + txo) + dx;
            float y0f = floorf(py), x0f = floorf(px);
            float wy1 = py - y0f, wx1 = px - x0f;
            float wy0 = 1.f - wy1, wx0 = 1.f - wx1;
            int y0 = (int)y0f, x0 = (int)x0f;
            bool yin0 = ((unsigned)y0 < 64u), yin1 = ((unsigned)(y0+1) < 64u);
            bool xin0 = ((unsigned)x0 < 64u), xin1 = ((unsigned)(x0+1) < 64u);
            float w00 = mk*wy0*wx0, w01 = mk*wy0*wx1;
            float w10 = mk*wy1*wx0, w11 = mk*wy1*wx1;
            const __half* base = g_cat_hi + (size_t)(b << 12)*512 + 256 + g*32 + l8*4;
            int i00 = (y0*64 + x0)*512;
            float a0 = 0.f, a1 = 0.f, a2 = 0.f, a3 = 0.f;
            auto acc4 = [&](int off, float w){
                uint2 u = *(const uint2*)(base + off);
                float2 p0 = __half22float2(*(__half2*)&u.x);
                float2 p1 = __half22float2(*(__half2*)&u.y);
                a0 += w*p0.x; a1 += w*p0.y; a2 += w*p1.x; a3 += w*p1.y;
            };
            if (yin0 && xin0) acc4(i00,             w00);
            if (yin0 && xin1) acc4(i00 + 512,       w01);
            if (yin1 && xin0) acc4(i00 + 32768,     w10);
            if (yin1 && xin1) acc4(i00 + 33280,     w11);
            __half2 h0 = __floats2half2_rn(a0, a1);
            __half2 h1 = __floats2half2_rn(a2, a3);
            uint2 o;
            o.x = *(uint32_t*)&h0;
            o.y = *(uint32_t*)&h1;
            *(uint2*)(colB + t*256 + g*32 + l8*4) = o;
        }
    }
}

// ---------------- launcher -------------------------------------------------------
extern "C" void kernel_launch(void* const* d_in, const int* in_sizes, int n_in,
                              void* d_out, int out_size){
    const float* fine      = (const float*)d_in[0];
    const float* coarse    = (const float*)d_in[1];
    const float* fs_attn_w = (const float*)d_in[2];
    const float* fs_conv_w = (const float*)d_in[3];
    const float* offset_w  = (const float*)d_in[4];
    const float* om_w      = (const float*)d_in[5];
    const float* om_b      = (const float*)d_in[6];
    const float* dcn_w     = (const float*)d_in[7];
    const float* dcn_b     = (const float*)d_in[8];
    float* out = (float*)d_out;
    (void)in_sizes; (void)n_in; (void)out_size;

    const int GSM = 98304;    // 2 stages x (A 16KB + B 32KB)
    const int WSM = 98304;    // wcomb: 2 stages x (AH,AL,BH) x 16KB
    cudaFuncSetAttribute(mmagemm<0>, cudaFuncAttributeMaxDynamicSharedMemorySize, GSM);
    cudaFuncSetAttribute(mmagemm<2>, cudaFuncAttributeMaxDynamicSharedMemorySize, GSM);
    cudaFuncSetAttribute(mmagemm<3>, cudaFuncAttributeMaxDynamicSharedMemorySize, GSM);
    cudaFuncSetAttribute(wcomb_mma,  cudaFuncAttributeMaxDynamicSharedMemorySize, WSM);

    gap_partial <<<128,  256>>>(fine);
    attn_kernel <<<4,    256>>>(fs_attn_w);
    prep_pix    <<<4096, 256>>>(fine, coarse);
    wprep       <<<5552, 256>>>(fs_conv_w, dcn_w, offset_w, om_w);
    wcomb_mma   <<<dim3(4, 2, 9), 256, WSM>>>();

    mmagemm<0> <<<128, 512, GSM>>>(nullptr, nullptr);
    mmagemm<2> <<<128, 512, GSM>>>(om_b,   nullptr);
    dcn_sample <<<2048, 256>>>();
    mmagemm<3> <<<128, 512, GSM>>>(dcn_b,  out);
}

// round 13
// speedup vs baseline: 1.0148x; 1.0148x over previous
#include <cuda_runtime.h>
#include <cuda_fp16.h>
#include <math.h>
#include <stdint.h>

#define B_   4
#define NPIX 16384
#define OMC  216
#define KDCN 2304

// ---------------- scratch (device globals) -----------------------------------
__device__ float g_part[32*B_*256];
__device__ float g_scale[B_*256];
__device__ float g_fine_cal[NPIX*256];
__device__ float g_om[NPIX*OMC];

__device__ __half g_fs_h[NPIX*256];                  // mode0 A (fp16)
__device__ __half g_cat_hi[NPIX*512];                // mode2 A (fp16); cols 256.. = 2*coarse_up
__device__ __half g_cols_hi[(size_t)NPIX*KDCN];      // mode3 A (fp16)

// weights
__device__ __half g_bt0h[256*256];                   // fs_conv_w^T fp16
__device__ __half g_bt2h[256*4608];                  // Wcomb^T fp16 (pad n 216->256)
__device__ __half g_bt3h[256*2304];                  // dcn_kernel^T fp16
__device__ __half g_ow_h[512*512], g_ow_l[512*512];  // offset_w split [c][f]
__device__ __half g_omt[9*256*512];                  // om_w^T fp16 [tap][n(pad)][f]

// ---------------- helpers ------------------------------------------------------
static __device__ __forceinline__ uint32_t smem_u32(const void* p){
    uint32_t a;
    asm("{ .reg .u64 t; cvta.to.shared.u64 t, %1; cvt.u32.u64 %0, t; }" : "=r"(a) : "l"(p));
    return a;
}
static __device__ __forceinline__ void cpa16(uint32_t dst, const void* src, int pbytes){
    asm volatile("cp.async.ca.shared.global [%0], [%1], 16, %2;"
                 :: "r"(dst), "l"(src), "r"(pbytes));
}
#define CP_COMMIT  asm volatile("cp.async.commit_group;" ::: "memory")
#define CP_WAIT2   asm volatile("cp.async.wait_group 2;" ::: "memory")
#define CP_WAIT1   asm volatile("cp.async.wait_group 1;" ::: "memory")
#define CP_WAIT0   asm volatile("cp.async.wait_group 0;" ::: "memory")
#define LDSM_X4(r, a) \
    asm volatile("ldmatrix.sync.aligned.m8n8.x4.shared.b16 {%0,%1,%2,%3}, [%4];" \
        : "=r"((r)[0]),"=r"((r)[1]),"=r"((r)[2]),"=r"((r)[3]) : "r"(a))
#define MMA16816(d, a, b0, b1) \
    asm volatile("mma.sync.aligned.m16n8k16.row.col.f32.f16.f16.f32 " \
        "{%0,%1,%2,%3}, {%4,%5,%6,%7}, {%8,%9}, {%0,%1,%2,%3};" \
        : "+f"((d)[0]),"+f"((d)[1]),"+f"((d)[2]),"+f"((d)[3]) \
        : "r"((a)[0]),"r"((a)[1]),"r"((a)[2]),"r"((a)[3]), "r"(b0), "r"(b1))

static __device__ __forceinline__ void split2(float v, __half& h, __half& l){
    h = __float2half_rn(v);
    l = __float2half_rn(v - __half2float(h));
}
static __device__ __forceinline__ uint32_t packh2(float x, float y){
    __half hx = __float2half_rn(x), hy = __float2half_rn(y);
    return (uint32_t)__half_as_ushort(hx) | ((uint32_t)__half_as_ushort(hy) << 16);
}

// ---------------- prep kernels ---------------------------------------------------
__global__ void gap_partial(const float* __restrict__ fine){
    int blk = blockIdx.x, b = blk >> 5, chunk = blk & 31, c = threadIdx.x;
    const float* p = fine + ((size_t)(b*4096 + chunk*128))*256 + c;
    float s = 0.f;
    #pragma unroll 8
    for (int r = 0; r < 128; r++) s += p[(size_t)r*256];
    g_part[blk*256 + c] = s;
}
__global__ void attn_kernel(const float* __restrict__ W){
    __shared__ float gp[256];
    int b = blockIdx.x, t = threadIdx.x;
    float s = 0.f;
    #pragma unroll
    for (int ch = 0; ch < 32; ch++) s += g_part[(b*32 + ch)*256 + t];
    gp[t] = s * (1.f/4096.f);
    __syncthreads();
    float acc = 0.f;
    for (int c = 0; c < 256; c++) acc += gp[c] * W[c*256 + t];
    g_scale[b*256 + t] = 1.f + 1.f/(1.f + expf(-acc));
}
// upsample(->cat coarse half) + fine*scale fp16 prep; 4 channels/thread, float4
__global__ void prep_pix(const float* __restrict__ fine, const float* __restrict__ coarse){
    int t = threadIdx.x;
    int m = blockIdx.x*4 + (t >> 6);
    int c = (t & 63)*4;
    int b = m >> 12, rem = m & 4095, y = rem >> 6, x = rem & 63;
    float fy = 0.5f*y - 0.25f, fx = 0.5f*x - 0.25f;
    float y0f = floorf(fy), x0f = floorf(fx);
    float wy1 = fy - y0f, wx1 = fx - x0f, wy0 = 1.f - wy1, wx0 = 1.f - wx1;
    int y0 = (int)y0f, x0 = (int)x0f;
    int y0c = min(max(y0,0),31), y1c = min(max(y0+1,0),31);
    int x0c = min(max(x0,0),31), x1c = min(max(x0+1,0),31);
    const float* cb = coarse + (size_t)(b*1024)*256 + c;
    float4 v00 = *(const float4*)(cb + (size_t)(y0c*32+x0c)*256);
    float4 v01 = *(const float4*)(cb + (size_t)(y0c*32+x1c)*256);
    float4 v10 = *(const float4*)(cb + (size_t)(y1c*32+x0c)*256);
    float4 v11 = *(const float4*)(cb + (size_t)(y1c*32+x1c)*256);
    float w00 = wy0*wx0, w01 = wy0*wx1, w10 = wy1*wx0, w11 = wy1*wx1;
    float4 v;
    v.x = w00*v00.x + w01*v01.x + w10*v10.x + w11*v11.x;
    v.y = w00*v00.y + w01*v01.y + w10*v10.y + w11*v11.y;
    v.z = w00*v00.z + w01*v01.z + w10*v10.z + w11*v11.z;
    v.w = w00*v00.w + w01*v01.w + w10*v10.w + w11*v11.w;
    uint2 co;
    co.x = packh2(2.f*v.x, 2.f*v.y);
    co.y = packh2(2.f*v.z, 2.f*v.w);
    *(uint2*)(g_cat_hi + (size_t)m*512 + 256 + c) = co;
    float4 f4 = *(const float4*)(fine + (size_t)m*256 + c);
    float4 s4 = *(const float4*)(g_scale + b*256 + c);
    uint2 fo;
    fo.x = packh2(f4.x*s4.x, f4.y*s4.y);
    fo.y = packh2(f4.z*s4.z, f4.w*s4.w);
    *(uint2*)(g_fs_h + (size_t)m*256 + c) = fo;
}

// ---- unified weight prep: one launch, blockIdx-range dispatch --------------------
__global__ void wprep(const float* __restrict__ fs_conv_w,
                      const float* __restrict__ dcn_w,
                      const float* __restrict__ offw,
                      const float* __restrict__ omw){
    __shared__ float tile[32][33];
    int blk = blockIdx.x;
    if (blk < 640){
        const float* W = (blk < 64) ? fs_conv_w : dcn_w;
        __half* T      = (blk < 64) ? g_bt0h    : g_bt3h;
        int KROWS      = (blk < 64) ? 256       : 2304;
        int b = (blk < 64) ? blk : blk - 64;
        int k0 = (b >> 3)*32, n0 = (b & 7)*32;
        int tx = threadIdx.x & 31, ty = threadIdx.x >> 5;
        #pragma unroll
        for (int i = 0; i < 4; i++)
            tile[ty + i*8][tx] = W[(size_t)(k0 + ty + i*8)*256 + n0 + tx];
        __syncthreads();
        #pragma unroll
        for (int i = 0; i < 4; i++)
            T[(size_t)(n0 + ty + i*8)*KROWS + k0 + tx] = __float2half_rn(tile[tx][ty + i*8]);
    } else if (blk < 1664){
        int i = (blk - 640)*256 + threadIdx.x;
        __half h, l; split2(offw[i], h, l);
        g_ow_h[i] = h; g_ow_l[i] = l;
    } else {
        int b = blk - 1664;
        int f = (b & 1)*256 + threadIdx.x;
        int n = (b >> 1) % 216;
        int tap = b / 432;
        g_omt[((size_t)tap*256 + n)*512 + f] =
            __float2half_rn(omw[((size_t)tap*512 + f)*216 + n]);
    }
}

// ---- Wcomb via HMMA (2-term: A hi/lo, B fp16) -----------------------------------
__global__ void __launch_bounds__(256)
wcomb_mma(){
    constexpr int Kk = 512, NC = 8;
    extern __shared__ __align__(16) char smem[];
    uint32_t sb = smem_u32(smem);
    int tid = threadIdx.x, lane = tid & 31, wid = tid >> 5;
    int m0 = blockIdx.x*128, n0 = blockIdx.y*128, tap = blockIdx.z;
    int wm = wid >> 2, wn = wid & 3;
    const __half* Bh = g_omt + (size_t)tap*256*512;

    auto load_chunk = [&](int stage, int k0){
        uint32_t base = sb + stage*49152;
        #pragma unroll
        for (int u = 0; u < 4; u++){
            int idx = tid + u*256;
            int row = idx >> 3, ch = idx & 7;
            uint32_t d = base + (uint32_t)(row*128 + ((ch ^ (row & 7)) << 4));
            size_t aoff = (size_t)(m0 + row)*Kk + k0 + ch*8;
            size_t boff = (size_t)(n0 + row)*Kk + k0 + ch*8;
            cpa16(d,         g_ow_h + aoff, 16);
            cpa16(d + 16384, g_ow_l + aoff, 16);
            cpa16(d + 32768, Bh + boff, 16);
        }
    };

    int rbase = wm*64 + ((lane >> 3) & 1)*8 + (lane & 7);
    int khA   = lane >> 4;
    int nbase = wn*32 + ((lane >> 4) & 1)*8 + (lane & 7);
    int khB   = (lane >> 3) & 1;
    uint32_t aswz = (uint32_t)(rbase & 7), bswz = (uint32_t)(nbase & 7);

    float acc[4][4][4];
    #pragma unroll
    for (int i = 0; i < 4; i++)
        #pragma unroll
        for (int j = 0; j < 4; j++)
            #pragma unroll
            for (int q = 0; q < 4; q++) acc[i][j][q] = 0.f;

    load_chunk(0, 0);
    CP_COMMIT;
    for (int c = 0; c < NC; c++){
        if (c + 1 < NC) load_chunk((c + 1) & 1, (c + 1)*64);
        CP_COMMIT;
        if (c + 1 < NC) CP_WAIT1; else CP_WAIT0;
        __syncthreads();
        uint32_t base = sb + (c & 1)*49152;
        #pragma unroll
        for (int ks = 0; ks < 4; ks++){
            uint32_t aH[4][4], aL[4][4], bH[2][4];
            #pragma unroll
            for (int mi = 0; mi < 4; mi++){
                uint32_t off = base + (uint32_t)((rbase + mi*16)*128
                             + ((((uint32_t)(ks*2 + khA)) ^ aswz) << 4));
                LDSM_X4(aH[mi], off);
                LDSM_X4(aL[mi], off + 16384);
            }
            #pragma unroll
            for (int nb = 0; nb < 2; nb++){
                uint32_t off = base + 32768 + (uint32_t)((nbase + nb*16)*128
                             + ((((uint32_t)(ks*2 + khB)) ^ bswz) << 4));
                LDSM_X4(bH[nb], off);
            }
            #pragma unroll
            for (int mi = 0; mi < 4; mi++)
                #pragma unroll
                for (int nj = 0; nj < 4; nj++){
                    uint32_t h0 = bH[nj >> 1][(nj & 1)*2], h1 = bH[nj >> 1][(nj & 1)*2 + 1];
                    MMA16816(acc[mi][nj], aH[mi], h0, h1);
                    MMA16816(acc[mi][nj], aL[mi], h0, h1);
                }
        }
        __syncthreads();
    }

    int g = lane >> 2, th = lane & 3;
    #pragma unroll
    for (int mi = 0; mi < 4; mi++){
        #pragma unroll
        for (int nj = 0; nj < 4; nj++){
            int col = n0 + wn*32 + nj*8 + th*2;
            float* a = acc[mi][nj];
            #pragma unroll
            for (int half = 0; half < 2; half++){
                int m = m0 + wm*64 + mi*16 + g + half*8;
                if (col < OMC){
                    g_bt2h[(size_t)col*4608 + tap*512 + m]     = __float2half_rn(a[half*2]);
                    g_bt2h[(size_t)(col+1)*4608 + tap*512 + m] = __float2half_rn(a[half*2+1]);
                }
            }
        }
    }
}

// ------- warp-MMA GEMM, 1-term fp16, BM128 BN128 BK64, 3-stage cp.async ---------
// MODE 0: fine_cal = fs_h @ bt0                (K=256)
// MODE 2: om = im2col(cat_hi) @ bt2 + bias      (K=4608, n<216)
// MODE 3: out = relu(cols_hi @ bt3 + b) + fc    (K=2304)
template<int MODE>
__global__ void __launch_bounds__(256)
mmagemm(const float* __restrict__ bias, float* __restrict__ outp){
    constexpr int Kk = (MODE==0) ? 256 : (MODE==2) ? 4608 : 2304;
    constexpr int NC = Kk / 64;
    constexpr uint32_t STAGE = 32768;
    const __half* Ah = (MODE==0) ? g_fs_h : (MODE==2) ? g_cat_hi : g_cols_hi;
    const __half* Bh = (MODE==0) ? g_bt0h : (MODE==2) ? g_bt2h : g_bt3h;

    extern __shared__ __align__(16) char smem[];
    uint32_t sb = smem_u32(smem);
    int tid = threadIdx.x, lane = tid & 31, wid = tid >> 5;
    int m0 = blockIdx.x*128, n0 = blockIdx.y*128;
    int wm = wid >> 2, wn = wid & 3;

    auto load_chunk = [&](int stage, int k0){
        uint32_t base = sb + stage*STAGE;
        #pragma unroll
        for (int u = 0; u < 4; u++){
            int idx = tid + u*256;
            int row = idx >> 3, ch = idx & 7;
            uint32_t d = base + (uint32_t)(row*128 + ((ch ^ (row & 7)) << 4));
            size_t boff = (size_t)(n0 + row)*Kk + k0 + ch*8;
            cpa16(d + 16384, Bh + boff, 16);
            if (MODE == 2){
                int m = m0 + row, bb = m >> 12, rem = m & 4095;
                int yy = rem >> 6, xx = rem & 63;
                int tap = k0 >> 9, cc = (k0 & 511) + ch*8;
                int ny = yy + tap/3 - 1, nx = xx + tap%3 - 1;
                bool ok = ((unsigned)ny < 64u) && ((unsigned)nx < 64u);
                size_t aoff = ok ? ((size_t)((bb << 12) + ny*64 + nx)*512 + cc) : 0;
                cpa16(d, Ah + aoff, ok ? 16 : 0);
            } else {
                size_t aoff = (size_t)(m0 + row)*Kk + k0 + ch*8;
                cpa16(d, Ah + aoff, 16);
            }
        }
    };

    int rbase = wm*64 + ((lane >> 3) & 1)*8 + (lane & 7);
    int khA   = lane >> 4;
    int nbase = wn*32 + ((lane >> 4) & 1)*8 + (lane & 7);
    int khB   = (lane >> 3) & 1;
    uint32_t aswz = (uint32_t)(rbase & 7), bswz = (uint32_t)(nbase & 7);

    float acc[4][4][4];
    #pragma unroll
    for (int i = 0; i < 4; i++)
        #pragma unroll
        for (int j = 0; j < 4; j++)
            #pragma unroll
            for (int q = 0; q < 4; q++) acc[i][j][q] = 0.f;

    // 3-stage pipeline
    load_chunk(0, 0); CP_COMMIT;
    if (NC > 1){ load_chunk(1, 64); CP_COMMIT; }
    for (int c = 0; c < NC; c++){
        if (c + 2 < NC){ load_chunk((c + 2) % 3, (c + 2)*64); CP_COMMIT; }
        if (c + 2 < NC)      CP_WAIT2;
        else if (c + 1 < NC) CP_WAIT1;
        else                 CP_WAIT0;
        __syncthreads();
        uint32_t base = sb + (uint32_t)(c % 3)*STAGE;
        #pragma unroll
        for (int ks = 0; ks < 4; ks++){
            uint32_t aH[4][4], bH[2][4];
            #pragma unroll
            for (int mi = 0; mi < 4; mi++){
                uint32_t off = base + (uint32_t)((rbase + mi*16)*128
                             + ((((uint32_t)(ks*2 + khA)) ^ aswz) << 4));
                LDSM_X4(aH[mi], off);
            }
            #pragma unroll
            for (int nb = 0; nb < 2; nb++){
                uint32_t off = base + 16384 + (uint32_t)((nbase + nb*16)*128
                             + ((((uint32_t)(ks*2 + khB)) ^ bswz) << 4));
                LDSM_X4(bH[nb], off);
            }
            #pragma unroll
            for (int mi = 0; mi < 4; mi++)
                #pragma unroll
                for (int nj = 0; nj < 4; nj++){
                    uint32_t h0 = bH[nj >> 1][(nj & 1)*2], h1 = bH[nj >> 1][(nj & 1)*2 + 1];
                    MMA16816(acc[mi][nj], aH[mi], h0, h1);
                }
        }
        __syncthreads();
    }

    int g = lane >> 2, th = lane & 3;
    #pragma unroll
    for (int mi = 0; mi < 4; mi++){
        #pragma unroll
        for (int nj = 0; nj < 4; nj++){
            int col = n0 + wn*32 + nj*8 + th*2;
            float* a = acc[mi][nj];
            #pragma unroll
            for (int half = 0; half < 2; half++){
                int m = m0 + wm*64 + mi*16 + g + half*8;
                float x = a[half*2], y = a[half*2 + 1];
                if (MODE == 0){
                    *(float2*)(g_fine_cal + (size_t)m*256 + col) = make_float2(x, y);
                    *(uint32_t*)(g_cat_hi + (size_t)m*512 + col) = packh2(x, y);
                } else if (MODE == 2){
                    if (col < OMC)
                        *(float2*)(g_om + (size_t)m*OMC + col) =
                            make_float2(x + bias[col], y + bias[col + 1]);
                } else {
                    float2 fc = *(const float2*)(g_fine_cal + (size_t)m*256 + col);
                    float2 o;
                    o.x = fmaxf(x + bias[col],     0.f) + fc.x;
                    o.y = fmaxf(y + bias[col + 1], 0.f) + fc.y;
                    *(float2*)(outp + (size_t)m*256 + col) = o;
                }
            }
        }
    }
}

// -------- deformable sampling: 1 warp = 1 pixel, uint2 gathers from cat_hi -------
__global__ __launch_bounds__(256)
void dcn_sample(){
    __shared__ float oms[8*OMC];
    int tid = threadIdx.x;
    int pixBase = blockIdx.x * 8;
    for (int i = tid; i < 8*OMC; i += 256)
        oms[i] = g_om[(size_t)pixBase*OMC + i];
    __syncthreads();

    int wid = tid >> 5, lane = tid & 31;
    int g4 = lane >> 3, l8 = lane & 7;
    int m = pixBase + wid;
    int b = m >> 12, rem = m & 4095, y = rem >> 6, x = rem & 63;
    const float* om = oms + wid*OMC;
    __half* colB = g_cols_hi + (size_t)m*KDCN;

    #pragma unroll
    for (int t = 0; t < 9; t++){
        int tyo = t/3 - 1, txo = t - (t/3)*3 - 1;
        #pragma unroll
        for (int gp = 0; gp < 2; gp++){
            int g = gp*4 + g4;
            float dy = om[g*18 + t*2];
            float dx = om[g*18 + t*2 + 1];
            float mk = 1.f / (1.f + __expf(-om[144 + g*9 + t]));  // (2*sig)*0.5
            float py = (float)(y + tyo) + dy;
            float px = (float)(x + txo) + dx;
            float y0f = floorf(py), x0f = floorf(px);
            float wy1 = py - y0f, wx1 = px - x0f;
            float wy0 = 1.f - wy1, wx0 = 1.f - wx1;
            int y0 = (int)y0f, x0 = (int)x0f;
            bool yin0 = ((unsigned)y0 < 64u), yin1 = ((unsigned)(y0+1) < 64u);
            bool xin0 = ((unsigned)x0 < 64u), xin1 = ((unsigned)(x0+1) < 64u);
            float w00 = mk*wy0*wx0, w01 = mk*wy0*wx1;
            float w10 = mk*wy1*wx0, w11 = mk*wy1*wx1;
            const __half* base = g_cat_hi + (size_t)(b << 12)*512 + 256 + g*32 + l8*4;
            int i00 = (y0*64 + x0)*512;
            float a0 = 0.f, a1 = 0.f, a2 = 0.f, a3 = 0.f;
            auto acc4 = [&](int off, float w){
                uint2 u = *(const uint2*)(base + off);
                float2 p0 = __half22float2(*(__half2*)&u.x);
                float2 p1 = __half22float2(*(__half2*)&u.y);
                a0 += w*p0.x; a1 += w*p0.y; a2 += w*p1.x; a3 += w*p1.y;
            };
            if (yin0 && xin0) acc4(i00,             w00);
            if (yin0 && xin1) acc4(i00 + 512,       w01);
            if (yin1 && xin0) acc4(i00 + 32768,     w10);
            if (yin1 && xin1) acc4(i00 + 33280,     w11);
            __half2 h0 = __floats2half2_rn(a0, a1);
            __half2 h1 = __floats2half2_rn(a2, a3);
            uint2 o;
            o.x = *(uint32_t*)&h0;
            o.y = *(uint32_t*)&h1;
            *(uint2*)(colB + t*256 + g*32 + l8*4) = o;
        }
    }
}

// ---------------- launcher -------------------------------------------------------
extern "C" void kernel_launch(void* const* d_in, const int* in_sizes, int n_in,
                              void* d_out, int out_size){
    const float* fine      = (const float*)d_in[0];
    const float* coarse    = (const float*)d_in[1];
    const float* fs_attn_w = (const float*)d_in[2];
    const float* fs_conv_w = (const float*)d_in[3];
    const float* offset_w  = (const float*)d_in[4];
    const float* om_w      = (const float*)d_in[5];
    const float* om_b      = (const float*)d_in[6];
    const float* dcn_w     = (const float*)d_in[7];
    const float* dcn_b     = (const float*)d_in[8];
    float* out = (float*)d_out;
    (void)in_sizes; (void)n_in; (void)out_size;

    const int GSM = 98304;    // 3 stages x (AH,BH) x 16KB
    const int WSM = 98304;    // wcomb: 2 stages x (AH,AL,BH) x 16KB
    cudaFuncSetAttribute(mmagemm<0>, cudaFuncAttributeMaxDynamicSharedMemorySize, GSM);
    cudaFuncSetAttribute(mmagemm<2>, cudaFuncAttributeMaxDynamicSharedMemorySize, GSM);
    cudaFuncSetAttribute(mmagemm<3>, cudaFuncAttributeMaxDynamicSharedMemorySize, GSM);
    cudaFuncSetAttribute(wcomb_mma,  cudaFuncAttributeMaxDynamicSharedMemorySize, WSM);

    gap_partial <<<128,  256>>>(fine);
    attn_kernel <<<4,    256>>>(fs_attn_w);
    prep_pix    <<<4096, 256>>>(fine, coarse);
    wprep       <<<5552, 256>>>(fs_conv_w, dcn_w, offset_w, om_w);
    wcomb_mma   <<<dim3(4, 2, 9), 256, WSM>>>();

    mmagemm<0> <<<dim3(128, 2), 256, GSM>>>(nullptr, nullptr);
    mmagemm<2> <<<dim3(128, 2), 256, GSM>>>(om_b,   nullptr);
    dcn_sample <<<2048, 256>>>();
    mmagemm<3> <<<dim3(128, 2), 256, GSM>>>(dcn_b,  out);
}

// round 14
// speedup vs baseline: 1.0504x; 1.0351x over previous
#include <cuda_runtime.h>
#include <cuda_fp16.h>
#include <math.h>
#include <stdint.h>

#define B_   4
#define NPIX 16384
#define OMC  216
#define KDCN 2304

// ---------------- scratch (device globals) -----------------------------------
__device__ float g_part[32*B_*256];
__device__ float g_scale[B_*256];
__device__ float g_fine_cal[NPIX*256];
__device__ float g_om[NPIX*OMC];

__device__ __half g_fs_h[NPIX*256];                  // mode0 A (fp16)
__device__ __half g_cat_hi[NPIX*512];                // mode2 A (fp16); cols 256.. = 2*coarse_up
__device__ __half g_cols_hi[(size_t)NPIX*KDCN];      // mode3 A (fp16)

// weights
__device__ __half g_bt0h[256*256];                   // fs_conv_w^T fp16
__device__ __half g_bt2h[256*4608];                  // Wcomb^T fp16 (pad n 216->256)
__device__ __half g_bt3h[256*2304];                  // dcn_kernel^T fp16
__device__ __half g_ow_h[512*512], g_ow_l[512*512];  // offset_w split [c][f]
__device__ __half g_omt[9*256*512];                  // om_w^T fp16 [tap][n(pad)][f]

// ---------------- helpers ------------------------------------------------------
static __device__ __forceinline__ uint32_t smem_u32(const void* p){
    uint32_t a;
    asm("{ .reg .u64 t; cvta.to.shared.u64 t, %1; cvt.u32.u64 %0, t; }" : "=r"(a) : "l"(p));
    return a;
}
static __device__ __forceinline__ void cpa16(uint32_t dst, const void* src, int pbytes){
    asm volatile("cp.async.ca.shared.global [%0], [%1], 16, %2;"
                 :: "r"(dst), "l"(src), "r"(pbytes));
}
#define CP_COMMIT  asm volatile("cp.async.commit_group;" ::: "memory")
#define CP_WAIT1   asm volatile("cp.async.wait_group 1;" ::: "memory")
#define CP_WAIT0   asm volatile("cp.async.wait_group 0;" ::: "memory")
#define LDSM_X4(r, a) \
    asm volatile("ldmatrix.sync.aligned.m8n8.x4.shared.b16 {%0,%1,%2,%3}, [%4];" \
        : "=r"((r)[0]),"=r"((r)[1]),"=r"((r)[2]),"=r"((r)[3]) : "r"(a))
#define MMA16816(d, a, b0, b1) \
    asm volatile("mma.sync.aligned.m16n8k16.row.col.f32.f16.f16.f32 " \
        "{%0,%1,%2,%3}, {%4,%5,%6,%7}, {%8,%9}, {%0,%1,%2,%3};" \
        : "+f"((d)[0]),"+f"((d)[1]),"+f"((d)[2]),"+f"((d)[3]) \
        : "r"((a)[0]),"r"((a)[1]),"r"((a)[2]),"r"((a)[3]), "r"(b0), "r"(b1))

static __device__ __forceinline__ void split2(float v, __half& h, __half& l){
    h = __float2half_rn(v);
    l = __float2half_rn(v - __half2float(h));
}
static __device__ __forceinline__ uint32_t packh2(float x, float y){
    __half hx = __float2half_rn(x), hy = __float2half_rn(y);
    return (uint32_t)__half_as_ushort(hx) | ((uint32_t)__half_as_ushort(hy) << 16);
}

// ---------------- prep kernels ---------------------------------------------------
__global__ void gap_partial(const float* __restrict__ fine){
    int blk = blockIdx.x, b = blk >> 5, chunk = blk & 31, c = threadIdx.x;
    const float* p = fine + ((size_t)(b*4096 + chunk*128))*256 + c;
    float s = 0.f;
    #pragma unroll 8
    for (int r = 0; r < 128; r++) s += p[(size_t)r*256];
    g_part[blk*256 + c] = s;
}
__global__ void attn_kernel(const float* __restrict__ W){
    __shared__ float gp[256];
    int b = blockIdx.x, t = threadIdx.x;
    float s = 0.f;
    #pragma unroll
    for (int ch = 0; ch < 32; ch++) s += g_part[(b*32 + ch)*256 + t];
    gp[t] = s * (1.f/4096.f);
    __syncthreads();
    float acc = 0.f;
    for (int c = 0; c < 256; c++) acc += gp[c] * W[c*256 + t];
    g_scale[b*256 + t] = 1.f + 1.f/(1.f + expf(-acc));
}
// upsample(->cat coarse half) + fine*scale fp16 prep; 4 channels/thread, float4
__global__ void prep_pix(const float* __restrict__ fine, const float* __restrict__ coarse){
    int t = threadIdx.x;
    int m = blockIdx.x*4 + (t >> 6);
    int c = (t & 63)*4;
    int b = m >> 12, rem = m & 4095, y = rem >> 6, x = rem & 63;
    float fy = 0.5f*y - 0.25f, fx = 0.5f*x - 0.25f;
    float y0f = floorf(fy), x0f = floorf(fx);
    float wy1 = fy - y0f, wx1 = fx - x0f, wy0 = 1.f - wy1, wx0 = 1.f - wx1;
    int y0 = (int)y0f, x0 = (int)x0f;
    int y0c = min(max(y0,0),31), y1c = min(max(y0+1,0),31);
    int x0c = min(max(x0,0),31), x1c = min(max(x0+1,0),31);
    const float* cb = coarse + (size_t)(b*1024)*256 + c;
    float4 v00 = *(const float4*)(cb + (size_t)(y0c*32+x0c)*256);
    float4 v01 = *(const float4*)(cb + (size_t)(y0c*32+x1c)*256);
    float4 v10 = *(const float4*)(cb + (size_t)(y1c*32+x0c)*256);
    float4 v11 = *(const float4*)(cb + (size_t)(y1c*32+x1c)*256);
    float w00 = wy0*wx0, w01 = wy0*wx1, w10 = wy1*wx0, w11 = wy1*wx1;
    float4 v;
    v.x = w00*v00.x + w01*v01.x + w10*v10.x + w11*v11.x;
    v.y = w00*v00.y + w01*v01.y + w10*v10.y + w11*v11.y;
    v.z = w00*v00.z + w01*v01.z + w10*v10.z + w11*v11.z;
    v.w = w00*v00.w + w01*v01.w + w10*v10.w + w11*v11.w;
    uint2 co;
    co.x = packh2(2.f*v.x, 2.f*v.y);
    co.y = packh2(2.f*v.z, 2.f*v.w);
    *(uint2*)(g_cat_hi + (size_t)m*512 + 256 + c) = co;
    float4 f4 = *(const float4*)(fine + (size_t)m*256 + c);
    float4 s4 = *(const float4*)(g_scale + b*256 + c);
    uint2 fo;
    fo.x = packh2(f4.x*s4.x, f4.y*s4.y);
    fo.y = packh2(f4.z*s4.z, f4.w*s4.w);
    *(uint2*)(g_fs_h + (size_t)m*256 + c) = fo;
}

// ---- unified weight prep: one launch, blockIdx-range dispatch --------------------
__global__ void wprep(const float* __restrict__ fs_conv_w,
                      const float* __restrict__ dcn_w,
                      const float* __restrict__ offw,
                      const float* __restrict__ omw){
    __shared__ float tile[32][33];
    int blk = blockIdx.x;
    if (blk < 640){
        const float* W = (blk < 64) ? fs_conv_w : dcn_w;
        __half* T      = (blk < 64) ? g_bt0h    : g_bt3h;
        int KROWS      = (blk < 64) ? 256       : 2304;
        int b = (blk < 64) ? blk : blk - 64;
        int k0 = (b >> 3)*32, n0 = (b & 7)*32;
        int tx = threadIdx.x & 31, ty = threadIdx.x >> 5;
        #pragma unroll
        for (int i = 0; i < 4; i++)
            tile[ty + i*8][tx] = W[(size_t)(k0 + ty + i*8)*256 + n0 + tx];
        __syncthreads();
        #pragma unroll
        for (int i = 0; i < 4; i++)
            T[(size_t)(n0 + ty + i*8)*KROWS + k0 + tx] = __float2half_rn(tile[tx][ty + i*8]);
    } else if (blk < 1664){
        int i = (blk - 640)*256 + threadIdx.x;
        __half h, l; split2(offw[i], h, l);
        g_ow_h[i] = h; g_ow_l[i] = l;
    } else {
        int b = blk - 1664;
        int f = (b & 1)*256 + threadIdx.x;
        int n = (b >> 1) % 216;
        int tap = b / 432;
        g_omt[((size_t)tap*256 + n)*512 + f] =
            __float2half_rn(omw[((size_t)tap*512 + f)*216 + n]);
    }
}

// ---- Wcomb via HMMA (2-term: A hi/lo, B fp16) -----------------------------------
__global__ void __launch_bounds__(256)
wcomb_mma(){
    constexpr int Kk = 512, NC = 8;
    extern __shared__ __align__(16) char smem[];
    uint32_t sb = smem_u32(smem);
    int tid = threadIdx.x, lane = tid & 31, wid = tid >> 5;
    int m0 = blockIdx.x*128, n0 = blockIdx.y*128, tap = blockIdx.z;
    int wm = wid >> 2, wn = wid & 3;
    const __half* Bh = g_omt + (size_t)tap*256*512;

    auto load_chunk = [&](int stage, int k0){
        uint32_t base = sb + stage*49152;
        #pragma unroll
        for (int u = 0; u < 4; u++){
            int idx = tid + u*256;
            int row = idx >> 3, ch = idx & 7;
            uint32_t d = base + (uint32_t)(row*128 + ((ch ^ (row & 7)) << 4));
            size_t aoff = (size_t)(m0 + row)*Kk + k0 + ch*8;
            size_t boff = (size_t)(n0 + row)*Kk + k0 + ch*8;
            cpa16(d,         g_ow_h + aoff, 16);
            cpa16(d + 16384, g_ow_l + aoff, 16);
            cpa16(d + 32768, Bh + boff, 16);
        }
    };

    int rbase = wm*64 + ((lane >> 3) & 1)*8 + (lane & 7);
    int khA   = lane >> 4;
    int nbase = wn*32 + ((lane >> 4) & 1)*8 + (lane & 7);
    int khB   = (lane >> 3) & 1;
    uint32_t aswz = (uint32_t)(rbase & 7), bswz = (uint32_t)(nbase & 7);

    float acc[4][4][4];
    #pragma unroll
    for (int i = 0; i < 4; i++)
        #pragma unroll
        for (int j = 0; j < 4; j++)
            #pragma unroll
            for (int q = 0; q < 4; q++) acc[i][j][q] = 0.f;

    load_chunk(0, 0);
    CP_COMMIT;
    for (int c = 0; c < NC; c++){
        if (c + 1 < NC) load_chunk((c + 1) & 1, (c + 1)*64);
        CP_COMMIT;
        if (c + 1 < NC) CP_WAIT1; else CP_WAIT0;
        __syncthreads();
        uint32_t base = sb + (c & 1)*49152;
        #pragma unroll
        for (int ks = 0; ks < 4; ks++){
            uint32_t aH[4][4], aL[4][4], bH[2][4];
            #pragma unroll
            for (int mi = 0; mi < 4; mi++){
                uint32_t off = base + (uint32_t)((rbase + mi*16)*128
                             + ((((uint32_t)(ks*2 + khA)) ^ aswz) << 4));
                LDSM_X4(aH[mi], off);
                LDSM_X4(aL[mi], off + 16384);
            }
            #pragma unroll
            for (int nb = 0; nb < 2; nb++){
                uint32_t off = base + 32768 + (uint32_t)((nbase + nb*16)*128
                             + ((((uint32_t)(ks*2 + khB)) ^ bswz) << 4));
                LDSM_X4(bH[nb], off);
            }
            #pragma unroll
            for (int mi = 0; mi < 4; mi++)
                #pragma unroll
                for (int nj = 0; nj < 4; nj++){
                    uint32_t h0 = bH[nj >> 1][(nj & 1)*2], h1 = bH[nj >> 1][(nj & 1)*2 + 1];
                    MMA16816(acc[mi][nj], aH[mi], h0, h1);
                    MMA16816(acc[mi][nj], aL[mi], h0, h1);
                }
        }
        __syncthreads();
    }

    int g = lane >> 2, th = lane & 3;
    #pragma unroll
    for (int mi = 0; mi < 4; mi++){
        #pragma unroll
        for (int nj = 0; nj < 4; nj++){
            int col = n0 + wn*32 + nj*8 + th*2;
            float* a = acc[mi][nj];
            #pragma unroll
            for (int half = 0; half < 2; half++){
                int m = m0 + wm*64 + mi*16 + g + half*8;
                if (col < OMC){
                    g_bt2h[(size_t)col*4608 + tap*512 + m]     = __float2half_rn(a[half*2]);
                    g_bt2h[(size_t)(col+1)*4608 + tap*512 + m] = __float2half_rn(a[half*2+1]);
                }
            }
        }
    }
}

// ------- warp-MMA GEMM, 1-term fp16, BM128 BN128 BK64, 2-stage (3 CTAs/SM) ------
// MODE 0: fine_cal = fs_h @ bt0                (K=256)
// MODE 2: om = im2col(cat_hi) @ bt2 + bias      (K=4608, n<216)
// MODE 3: out = relu(cols_hi @ bt3 + b) + fc    (K=2304)
template<int MODE>
__global__ void __launch_bounds__(256)
mmagemm(const float* __restrict__ bias, float* __restrict__ outp){
    constexpr int Kk = (MODE==0) ? 256 : (MODE==2) ? 4608 : 2304;
    constexpr int NC = Kk / 64;
    constexpr uint32_t STAGE = 32768;
    const __half* Ah = (MODE==0) ? g_fs_h : (MODE==2) ? g_cat_hi : g_cols_hi;
    const __half* Bh = (MODE==0) ? g_bt0h : (MODE==2) ? g_bt2h : g_bt3h;

    extern __shared__ __align__(16) char smem[];
    uint32_t sb = smem_u32(smem);
    int tid = threadIdx.x, lane = tid & 31, wid = tid >> 5;
    int m0 = blockIdx.x*128, n0 = blockIdx.y*128;
    int wm = wid >> 2, wn = wid & 3;

    auto load_chunk = [&](int stage, int k0){
        uint32_t base = sb + stage*STAGE;
        #pragma unroll
        for (int u = 0; u < 4; u++){
            int idx = tid + u*256;
            int row = idx >> 3, ch = idx & 7;
            uint32_t d = base + (uint32_t)(row*128 + ((ch ^ (row & 7)) << 4));
            size_t boff = (size_t)(n0 + row)*Kk + k0 + ch*8;
            cpa16(d + 16384, Bh + boff, 16);
            if (MODE == 2){
                int m = m0 + row, bb = m >> 12, rem = m & 4095;
                int yy = rem >> 6, xx = rem & 63;
                int tap = k0 >> 9, cc = (k0 & 511) + ch*8;
                int ny = yy + tap/3 - 1, nx = xx + tap%3 - 1;
                bool ok = ((unsigned)ny < 64u) && ((unsigned)nx < 64u);
                size_t aoff = ok ? ((size_t)((bb << 12) + ny*64 + nx)*512 + cc) : 0;
                cpa16(d, Ah + aoff, ok ? 16 : 0);
            } else {
                size_t aoff = (size_t)(m0 + row)*Kk + k0 + ch*8;
                cpa16(d, Ah + aoff, 16);
            }
        }
    };

    int rbase = wm*64 + ((lane >> 3) & 1)*8 + (lane & 7);
    int khA   = lane >> 4;
    int nbase = wn*32 + ((lane >> 4) & 1)*8 + (lane & 7);
    int khB   = (lane >> 3) & 1;
    uint32_t aswz = (uint32_t)(rbase & 7), bswz = (uint32_t)(nbase & 7);

    float acc[4][4][4];
    #pragma unroll
    for (int i = 0; i < 4; i++)
        #pragma unroll
        for (int j = 0; j < 4; j++)
            #pragma unroll
            for (int q = 0; q < 4; q++) acc[i][j][q] = 0.f;

    load_chunk(0, 0);
    CP_COMMIT;
    for (int c = 0; c < NC; c++){
        if (c + 1 < NC) load_chunk((c + 1) & 1, (c + 1)*64);
        CP_COMMIT;
        if (c + 1 < NC) CP_WAIT1; else CP_WAIT0;
        __syncthreads();
        uint32_t base = sb + (c & 1)*STAGE;
        #pragma unroll
        for (int ks = 0; ks < 4; ks++){
            uint32_t aH[4][4], bH[2][4];
            #pragma unroll
            for (int mi = 0; mi < 4; mi++){
                uint32_t off = base + (uint32_t)((rbase + mi*16)*128
                             + ((((uint32_t)(ks*2 + khA)) ^ aswz) << 4));
                LDSM_X4(aH[mi], off);
            }
            #pragma unroll
            for (int nb = 0; nb < 2; nb++){
                uint32_t off = base + 16384 + (uint32_t)((nbase + nb*16)*128
                             + ((((uint32_t)(ks*2 + khB)) ^ bswz) << 4));
                LDSM_X4(bH[nb], off);
            }
            #pragma unroll
            for (int mi = 0; mi < 4; mi++)
                #pragma unroll
                for (int nj = 0; nj < 4; nj++){
                    uint32_t h0 = bH[nj >> 1][(nj & 1)*2], h1 = bH[nj >> 1][(nj & 1)*2 + 1];
                    MMA16816(acc[mi][nj], aH[mi], h0, h1);
                }
        }
        __syncthreads();
    }

    int g = lane >> 2, th = lane & 3;
    #pragma unroll
    for (int mi = 0; mi < 4; mi++){
        #pragma unroll
        for (int nj = 0; nj < 4; nj++){
            int col = n0 + wn*32 + nj*8 + th*2;
            float* a = acc[mi][nj];
            #pragma unroll
            for (int half = 0; half < 2; half++){
                int m = m0 + wm*64 + mi*16 + g + half*8;
                float x = a[half*2], y = a[half*2 + 1];
                if (MODE == 0){
                    *(float2*)(g_fine_cal + (size_t)m*256 + col) = make_float2(x, y);
                    *(uint32_t*)(g_cat_hi + (size_t)m*512 + col) = packh2(x, y);
                } else if (MODE == 2){
                    if (col < OMC)
                        *(float2*)(g_om + (size_t)m*OMC + col) =
                            make_float2(x + bias[col], y + bias[col + 1]);
                } else {
                    float2 fc = *(const float2*)(g_fine_cal + (size_t)m*256 + col);
                    float2 o;
                    o.x = fmaxf(x + bias[col],     0.f) + fc.x;
                    o.y = fmaxf(y + bias[col + 1], 0.f) + fc.y;
                    *(float2*)(outp + (size_t)m*256 + col) = o;
                }
            }
        }
    }
}

// -------- deformable sampling: 1 warp = 1 pixel, uint2 gathers from cat_hi -------
__global__ __launch_bounds__(256)
void dcn_sample(){
    __shared__ float oms[8*OMC];
    int tid = threadIdx.x;
    int pixBase = blockIdx.x * 8;
    for (int i = tid; i < 8*OMC; i += 256)
        oms[i] = g_om[(size_t)pixBase*OMC + i];
    __syncthreads();

    int wid = tid >> 5, lane = tid & 31;
    int g4 = lane >> 3, l8 = lane & 7;
    int m = pixBase + wid;
    int b = m >> 12, rem = m & 4095, y = rem >> 6, x = rem & 63;
    const float* om = oms + wid*OMC;
    __half* colB = g_cols_hi + (size_t)m*KDCN;

    #pragma unroll
    for (int t = 0; t < 9; t++){
        int tyo = t/3 - 1, txo = t - (t/3)*3 - 1;
        #pragma unroll
        for (int gp = 0; gp < 2; gp++){
            int g = gp*4 + g4;
            float dy = om[g*18 + t*2];
            float dx = om[g*18 + t*2 + 1];
            float mk = 1.f / (1.f + __expf(-om[144 + g*9 + t]));  // (2*sig)*0.5
            float py = (float)(y + tyo) + dy;
            float px = (float)(x + txo) + dx;
            float y0f = floorf(py), x0f = floorf(px);
            float wy1 = py - y0f, wx1 = px - x0f;
            float wy0 = 1.f - wy1, wx0 = 1.f - wx1;
            int y0 = (int)y0f, x0 = (int)x0f;
            bool yin0 = ((unsigned)y0 < 64u), yin1 = ((unsigned)(y0+1) < 64u);
            bool xin0 = ((unsigned)x0 < 64u), xin1 = ((unsigned)(x0+1) < 64u);
            float w00 = mk*wy0*wx0, w01 = mk*wy0*wx1;
            float w10 = mk*wy1*wx0, w11 = mk*wy1*wx1;
            const __half* base = g_cat_hi + (size_t)(b << 12)*512 + 256 + g*32 + l8*4;
            int i00 = (y0*64 + x0)*512;
            float a0 = 0.f, a1 = 0.f, a2 = 0.f, a3 = 0.f;
            auto acc4 = [&](int off, float w){
                uint2 u = *(const uint2*)(base + off);
                float2 p0 = __half22float2(*(__half2*)&u.x);
                float2 p1 = __half22float2(*(__half2*)&u.y);
                a0 += w*p0.x; a1 += w*p0.y; a2 += w*p1.x; a3 += w*p1.y;
            };
            if (yin0 && xin0) acc4(i00,             w00);
            if (yin0 && xin1) acc4(i00 + 512,       w01);
            if (yin1 && xin0) acc4(i00 + 32768,     w10);
            if (yin1 && xin1) acc4(i00 + 33280,     w11);
            __half2 h0 = __floats2half2_rn(a0, a1);
            __half2 h1 = __floats2half2_rn(a2, a3);
            uint2 o;
            o.x = *(uint32_t*)&h0;
            o.y = *(uint32_t*)&h1;
            *(uint2*)(colB + t*256 + g*32 + l8*4) = o;
        }
    }
}

// ---------------- launcher -------------------------------------------------------
extern "C" void kernel_launch(void* const* d_in, const int* in_sizes, int n_in,
                              void* d_out, int out_size){
    const float* fine      = (const float*)d_in[0];
    const float* coarse    = (const float*)d_in[1];
    const float* fs_attn_w = (const float*)d_in[2];
    const float* fs_conv_w = (const float*)d_in[3];
    const float* offset_w  = (const float*)d_in[4];
    const float* om_w      = (const float*)d_in[5];
    const float* om_b      = (const float*)d_in[6];
    const float* dcn_w     = (const float*)d_in[7];
    const float* dcn_b     = (const float*)d_in[8];
    float* out = (float*)d_out;
    (void)in_sizes; (void)n_in; (void)out_size;

    const int GSM = 65536;    // 2 stages x (AH,BH) x 16KB -> 3 CTAs/SM
    const int WSM = 98304;    // wcomb: 2 stages x (AH,AL,BH) x 16KB
    cudaFuncSetAttribute(mmagemm<0>, cudaFuncAttributeMaxDynamicSharedMemorySize, GSM);
    cudaFuncSetAttribute(mmagemm<2>, cudaFuncAttributeMaxDynamicSharedMemorySize, GSM);
    cudaFuncSetAttribute(mmagemm<3>, cudaFuncAttributeMaxDynamicSharedMemorySize, GSM);
    cudaFuncSetAttribute(wcomb_mma,  cudaFuncAttributeMaxDynamicSharedMemorySize, WSM);

    gap_partial <<<128,  256>>>(fine);
    attn_kernel <<<4,    256>>>(fs_attn_w);
    prep_pix    <<<4096, 256>>>(fine, coarse);
    wprep       <<<5552, 256>>>(fs_conv_w, dcn_w, offset_w, om_w);
    wcomb_mma   <<<dim3(4, 2, 9), 256, WSM>>>();

    mmagemm<0> <<<dim3(128, 2), 256, GSM>>>(nullptr, nullptr);
    mmagemm<2> <<<dim3(128, 2), 256, GSM>>>(om_b,   nullptr);
    dcn_sample <<<2048, 256>>>();
    mmagemm<3> <<<dim3(128, 2), 256, GSM>>>(dcn_b,  out);
}

// round 15
// speedup vs baseline: 1.1359x; 1.0814x over previous
#include <cuda_runtime.h>
#include <cuda_fp16.h>
#include <math.h>
#include <stdint.h>

#define B_   4
#define NPIX 16384
#define OMC  216
#define KDCN 2304

// ---------------- scratch (device globals) -----------------------------------
__device__ float g_part[32*B_*256];
__device__ float g_scale[B_*256];
__device__ float g_fine_cal[NPIX*256];
__device__ float g_om[NPIX*OMC];

__device__ __half g_fs_h[NPIX*256];                  // mode0 A (fp16)
__device__ __half g_cat_hi[NPIX*512];                // mode2 A (fp16); cols 256.. = 2*coarse_up
__device__ __half g_cols_hi[(size_t)NPIX*KDCN];      // mode3 A (fp16)

// weights
__device__ __half g_bt0h[256*256];                   // fs_conv_w^T fp16
__device__ __half g_bt2h[256*4608];                  // Wcomb^T fp16 (pad n 216->256)
__device__ __half g_bt3h[256*2304];                  // dcn_kernel^T fp16
__device__ __half g_ow_h[512*512], g_ow_l[512*512];  // offset_w split [c][f]
__device__ __half g_omt[9*256*512];                  // om_w^T fp16 [tap][n(pad)][f]

// ---------------- helpers ------------------------------------------------------
static __device__ __forceinline__ uint32_t smem_u32(const void* p){
    uint32_t a;
    asm("{ .reg .u64 t; cvta.to.shared.u64 t, %1; cvt.u32.u64 %0, t; }" : "=r"(a) : "l"(p));
    return a;
}
static __device__ __forceinline__ void cpa16(uint32_t dst, const void* src, int pbytes){
    asm volatile("cp.async.ca.shared.global [%0], [%1], 16, %2;"
                 :: "r"(dst), "l"(src), "r"(pbytes));
}
#define CP_COMMIT  asm volatile("cp.async.commit_group;" ::: "memory")
#define CP_WAIT1   asm volatile("cp.async.wait_group 1;" ::: "memory")
#define CP_WAIT0   asm volatile("cp.async.wait_group 0;" ::: "memory")
#define LDSM_X4(r, a) \
    asm volatile("ldmatrix.sync.aligned.m8n8.x4.shared.b16 {%0,%1,%2,%3}, [%4];" \
        : "=r"((r)[0]),"=r"((r)[1]),"=r"((r)[2]),"=r"((r)[3]) : "r"(a))
#define MMA16816(d, a, b0, b1) \
    asm volatile("mma.sync.aligned.m16n8k16.row.col.f32.f16.f16.f32 " \
        "{%0,%1,%2,%3}, {%4,%5,%6,%7}, {%8,%9}, {%0,%1,%2,%3};" \
        : "+f"((d)[0]),"+f"((d)[1]),"+f"((d)[2]),"+f"((d)[3]) \
        : "r"((a)[0]),"r"((a)[1]),"r"((a)[2]),"r"((a)[3]), "r"(b0), "r"(b1))

static __device__ __forceinline__ void split2(float v, __half& h, __half& l){
    h = __float2half_rn(v);
    l = __float2half_rn(v - __half2float(h));
}
static __device__ __forceinline__ uint32_t packh2(float x, float y){
    __half hx = __float2half_rn(x), hy = __float2half_rn(y);
    return (uint32_t)__half_as_ushort(hx) | ((uint32_t)__half_as_ushort(hy) << 16);
}

// ---------------- prep: pixel-side (needs g_scale) -------------------------------
__global__ void prep_pix(const float* __restrict__ fine, const float* __restrict__ coarse){
    int t = threadIdx.x;
    int m = blockIdx.x*4 + (t >> 6);
    int c = (t & 63)*4;
    int b = m >> 12, rem = m & 4095, y = rem >> 6, x = rem & 63;
    float fy = 0.5f*y - 0.25f, fx = 0.5f*x - 0.25f;
    float y0f = floorf(fy), x0f = floorf(fx);
    float wy1 = fy - y0f, wx1 = fx - x0f, wy0 = 1.f - wy1, wx0 = 1.f - wx1;
    int y0 = (int)y0f, x0 = (int)x0f;
    int y0c = min(max(y0,0),31), y1c = min(max(y0+1,0),31);
    int x0c = min(max(x0,0),31), x1c = min(max(x0+1,0),31);
    const float* cb = coarse + (size_t)(b*1024)*256 + c;
    float4 v00 = *(const float4*)(cb + (size_t)(y0c*32+x0c)*256);
    float4 v01 = *(const float4*)(cb + (size_t)(y0c*32+x1c)*256);
    float4 v10 = *(const float4*)(cb + (size_t)(y1c*32+x0c)*256);
    float4 v11 = *(const float4*)(cb + (size_t)(y1c*32+x1c)*256);
    float w00 = wy0*wx0, w01 = wy0*wx1, w10 = wy1*wx0, w11 = wy1*wx1;
    float4 v;
    v.x = w00*v00.x + w01*v01.x + w10*v10.x + w11*v11.x;
    v.y = w00*v00.y + w01*v01.y + w10*v10.y + w11*v11.y;
    v.z = w00*v00.z + w01*v01.z + w10*v10.z + w11*v11.z;
    v.w = w00*v00.w + w01*v01.w + w10*v10.w + w11*v11.w;
    uint2 co;
    co.x = packh2(2.f*v.x, 2.f*v.y);
    co.y = packh2(2.f*v.z, 2.f*v.w);
    *(uint2*)(g_cat_hi + (size_t)m*512 + 256 + c) = co;
    float4 f4 = *(const float4*)(fine + (size_t)m*256 + c);
    float4 s4 = *(const float4*)(g_scale + b*256 + c);
    uint2 fo;
    fo.x = packh2(f4.x*s4.x, f4.y*s4.y);
    fo.y = packh2(f4.z*s4.z, f4.w*s4.w);
    *(uint2*)(g_fs_h + (size_t)m*256 + c) = fo;
}

// ---- launch 1: weight prep + GAP partials (all independent) ----------------------
// [0,64)        tr16 fs_conv_w -> g_bt0h    [64,640)  tr16 dcn_w -> g_bt3h
// [640,1664)    owsplit offset_w            [1664,5552) omt transpose
// [5552,5680)   gap_partial
__global__ void wprep(const float* __restrict__ fs_conv_w,
                      const float* __restrict__ dcn_w,
                      const float* __restrict__ offw,
                      const float* __restrict__ omw,
                      const float* __restrict__ fine){
    __shared__ float tile[32][33];
    int blk = blockIdx.x;
    if (blk < 640){
        const float* W = (blk < 64) ? fs_conv_w : dcn_w;
        __half* T      = (blk < 64) ? g_bt0h    : g_bt3h;
        int KROWS      = (blk < 64) ? 256       : 2304;
        int b = (blk < 64) ? blk : blk - 64;
        int k0 = (b >> 3)*32, n0 = (b & 7)*32;
        int tx = threadIdx.x & 31, ty = threadIdx.x >> 5;
        #pragma unroll
        for (int i = 0; i < 4; i++)
            tile[ty + i*8][tx] = W[(size_t)(k0 + ty + i*8)*256 + n0 + tx];
        __syncthreads();
        #pragma unroll
        for (int i = 0; i < 4; i++)
            T[(size_t)(n0 + ty + i*8)*KROWS + k0 + tx] = __float2half_rn(tile[tx][ty + i*8]);
    } else if (blk < 1664){
        int i = (blk - 640)*256 + threadIdx.x;
        __half h, l; split2(offw[i], h, l);
        g_ow_h[i] = h; g_ow_l[i] = l;
    } else if (blk < 5552){
        int b = blk - 1664;
        int f = (b & 1)*256 + threadIdx.x;
        int n = (b >> 1) % 216;
        int tap = b / 432;
        g_omt[((size_t)tap*256 + n)*512 + f] =
            __float2half_rn(omw[((size_t)tap*512 + f)*216 + n]);
    } else {
        int gb = blk - 5552;                 // gap_partial
        int b = gb >> 5, chunk = gb & 31, c = threadIdx.x;
        const float* p = fine + ((size_t)(b*4096 + chunk*128))*256 + c;
        float s = 0.f;
        #pragma unroll 8
        for (int r = 0; r < 128; r++) s += p[(size_t)r*256];
        g_part[gb*256 + c] = s;
    }
}

// ---- launch 2: Wcomb HMMA (blocks 0..71) + attention scale (72..75) --------------
__global__ void __launch_bounds__(256)
wcomb_attn(const float* __restrict__ attn_w){
    if (blockIdx.x >= 72){
        __shared__ float gp[256];
        int b = blockIdx.x - 72, t = threadIdx.x;
        float s = 0.f;
        #pragma unroll
        for (int ch = 0; ch < 32; ch++) s += g_part[(b*32 + ch)*256 + t];
        gp[t] = s * (1.f/4096.f);
        __syncthreads();
        float acc = 0.f;
        for (int c = 0; c < 256; c++) acc += gp[c] * attn_w[c*256 + t];
        g_scale[b*256 + t] = 1.f + 1.f/(1.f + expf(-acc));
        return;
    }
    constexpr int Kk = 512, NC = 8;
    extern __shared__ __align__(16) char smem[];
    uint32_t sb = smem_u32(smem);
    int tid = threadIdx.x, lane = tid & 31, wid = tid >> 5;
    int blk = blockIdx.x;
    int tap = blk >> 3;
    int r8  = blk & 7;
    int m0 = (r8 >> 1)*128, n0 = (r8 & 1)*128;
    int wm = wid >> 2, wn = wid & 3;
    const bool act = (n0 + wn*32 < OMC);
    const __half* Bh = g_omt + (size_t)tap*256*512;

    auto load_chunk = [&](int stage, int k0){
        uint32_t base = sb + stage*49152;
        #pragma unroll
        for (int u = 0; u < 4; u++){
            int idx = tid + u*256;
            int row = idx >> 3, ch = idx & 7;
            uint32_t d = base + (uint32_t)(row*128 + ((ch ^ (row & 7)) << 4));
            size_t aoff = (size_t)(m0 + row)*Kk + k0 + ch*8;
            size_t boff = (size_t)(n0 + row)*Kk + k0 + ch*8;
            cpa16(d,         g_ow_h + aoff, 16);
            cpa16(d + 16384, g_ow_l + aoff, 16);
            cpa16(d + 32768, Bh + boff, 16);
        }
    };

    int rbase = wm*64 + ((lane >> 3) & 1)*8 + (lane & 7);
    int khA   = lane >> 4;
    int nbase = wn*32 + ((lane >> 4) & 1)*8 + (lane & 7);
    int khB   = (lane >> 3) & 1;
    uint32_t aswz = (uint32_t)(rbase & 7), bswz = (uint32_t)(nbase & 7);

    float acc[4][4][4];
    #pragma unroll
    for (int i = 0; i < 4; i++)
        #pragma unroll
        for (int j = 0; j < 4; j++)
            #pragma unroll
            for (int q = 0; q < 4; q++) acc[i][j][q] = 0.f;

    load_chunk(0, 0);
    CP_COMMIT;
    for (int c = 0; c < NC; c++){
        if (c + 1 < NC) load_chunk((c + 1) & 1, (c + 1)*64);
        CP_COMMIT;
        if (c + 1 < NC) CP_WAIT1; else CP_WAIT0;
        __syncthreads();
        if (act){
            uint32_t base = sb + (c & 1)*49152;
            #pragma unroll
            for (int ks = 0; ks < 4; ks++){
                uint32_t aH[4][4], aL[4][4], bH[2][4];
                #pragma unroll
                for (int mi = 0; mi < 4; mi++){
                    uint32_t off = base + (uint32_t)((rbase + mi*16)*128
                                 + ((((uint32_t)(ks*2 + khA)) ^ aswz) << 4));
                    LDSM_X4(aH[mi], off);
                    LDSM_X4(aL[mi], off + 16384);
                }
                #pragma unroll
                for (int nb = 0; nb < 2; nb++){
                    uint32_t off = base + 32768 + (uint32_t)((nbase + nb*16)*128
                                 + ((((uint32_t)(ks*2 + khB)) ^ bswz) << 4));
                    LDSM_X4(bH[nb], off);
                }
                #pragma unroll
                for (int mi = 0; mi < 4; mi++)
                    #pragma unroll
                    for (int nj = 0; nj < 4; nj++){
                        uint32_t h0 = bH[nj >> 1][(nj & 1)*2], h1 = bH[nj >> 1][(nj & 1)*2 + 1];
                        MMA16816(acc[mi][nj], aH[mi], h0, h1);
                        MMA16816(acc[mi][nj], aL[mi], h0, h1);
                    }
            }
        }
        __syncthreads();
    }

    int g = lane >> 2, th = lane & 3;
    #pragma unroll
    for (int mi = 0; mi < 4; mi++){
        #pragma unroll
        for (int nj = 0; nj < 4; nj++){
            int col = n0 + wn*32 + nj*8 + th*2;
            float* a = acc[mi][nj];
            #pragma unroll
            for (int half = 0; half < 2; half++){
                int m = m0 + wm*64 + mi*16 + g + half*8;
                if (col < OMC){
                    g_bt2h[(size_t)col*4608 + tap*512 + m]     = __float2half_rn(a[half*2]);
                    g_bt2h[(size_t)(col+1)*4608 + tap*512 + m] = __float2half_rn(a[half*2+1]);
                }
            }
        }
    }
}

// ------- warp-MMA GEMM, 1-term fp16, BM128 BN128 BK64, 2-stage (3 CTAs/SM) ------
// MODE 0: fine_cal = fs_h @ bt0                (K=256)
// MODE 2: om = im2col(cat_hi) @ bt2 + bias      (K=4608, n<216; pad warps skip MMA)
// MODE 3: out = relu(cols_hi @ bt3 + b) + fc    (K=2304)
template<int MODE>
__global__ void __launch_bounds__(256)
mmagemm(const float* __restrict__ bias, float* __restrict__ outp){
    constexpr int Kk = (MODE==0) ? 256 : (MODE==2) ? 4608 : 2304;
    constexpr int NC = Kk / 64;
    constexpr uint32_t STAGE = 32768;
    const __half* Ah = (MODE==0) ? g_fs_h : (MODE==2) ? g_cat_hi : g_cols_hi;
    const __half* Bh = (MODE==0) ? g_bt0h : (MODE==2) ? g_bt2h : g_bt3h;

    extern __shared__ __align__(16) char smem[];
    uint32_t sb = smem_u32(smem);
    int tid = threadIdx.x, lane = tid & 31, wid = tid >> 5;
    int m0 = blockIdx.x*128, n0 = blockIdx.y*128;
    int wm = wid >> 2, wn = wid & 3;
    const bool act = (MODE != 2) || (n0 + wn*32 < OMC);

    auto load_chunk = [&](int stage, int k0){
        uint32_t base = sb + stage*STAGE;
        #pragma unroll
        for (int u = 0; u < 4; u++){
            int idx = tid + u*256;
            int row = idx >> 3, ch = idx & 7;
            uint32_t d = base + (uint32_t)(row*128 + ((ch ^ (row & 7)) << 4));
            size_t boff = (size_t)(n0 + row)*Kk + k0 + ch*8;
            cpa16(d + 16384, Bh + boff, 16);
            if (MODE == 2){
                int m = m0 + row, bb = m >> 12, rem = m & 4095;
                int yy = rem >> 6, xx = rem & 63;
                int tap = k0 >> 9, cc = (k0 & 511) + ch*8;
                int ny = yy + tap/3 - 1, nx = xx + tap%3 - 1;
                bool ok = ((unsigned)ny < 64u) && ((unsigned)nx < 64u);
                size_t aoff = ok ? ((size_t)((bb << 12) + ny*64 + nx)*512 + cc) : 0;
                cpa16(d, Ah + aoff, ok ? 16 : 0);
            } else {
                size_t aoff = (size_t)(m0 + row)*Kk + k0 + ch*8;
                cpa16(d, Ah + aoff, 16);
            }
        }
    };

    int rbase = wm*64 + ((lane >> 3) & 1)*8 + (lane & 7);
    int khA   = lane >> 4;
    int nbase = wn*32 + ((lane >> 4) & 1)*8 + (lane & 7);
    int khB   = (lane >> 3) & 1;
    uint32_t aswz = (uint32_t)(rbase & 7), bswz = (uint32_t)(nbase & 7);

    float acc[4][4][4];
    #pragma unroll
    for (int i = 0; i < 4; i++)
        #pragma unroll
        for (int j = 0; j < 4; j++)
            #pragma unroll
            for (int q = 0; q < 4; q++) acc[i][j][q] = 0.f;

    load_chunk(0, 0);
    CP_COMMIT;
    for (int c = 0; c < NC; c++){
        if (c + 1 < NC) load_chunk((c + 1) & 1, (c + 1)*64);
        CP_COMMIT;
        if (c + 1 < NC) CP_WAIT1; else CP_WAIT0;
        __syncthreads();
        if (act){
            uint32_t base = sb + (c & 1)*STAGE;
            #pragma unroll
            for (int ks = 0; ks < 4; ks++){
                uint32_t aH[4][4], bH[2][4];
                #pragma unroll
                for (int mi = 0; mi < 4; mi++){
                    uint32_t off = base + (uint32_t)((rbase + mi*16)*128
                                 + ((((uint32_t)(ks*2 + khA)) ^ aswz) << 4));
                    LDSM_X4(aH[mi], off);
                }
                #pragma unroll
                for (int nb = 0; nb < 2; nb++){
                    uint32_t off = base + 16384 + (uint32_t)((nbase + nb*16)*128
                                 + ((((uint32_t)(ks*2 + khB)) ^ bswz) << 4));
                    LDSM_X4(bH[nb], off);
                }
                #pragma unroll
                for (int mi = 0; mi < 4; mi++)
                    #pragma unroll
                    for (int nj = 0; nj < 4; nj++){
                        uint32_t h0 = bH[nj >> 1][(nj & 1)*2], h1 = bH[nj >> 1][(nj & 1)*2 + 1];
                        MMA16816(acc[mi][nj], aH[mi], h0, h1);
                    }
            }
        }
        __syncthreads();
    }

    if (!act) return;
    int g = lane >> 2, th = lane & 3;
    #pragma unroll
    for (int mi = 0; mi < 4; mi++){
        #pragma unroll
        for (int nj = 0; nj < 4; nj++){
            int col = n0 + wn*32 + nj*8 + th*2;
            float* a = acc[mi][nj];
            #pragma unroll
            for (int half = 0; half < 2; half++){
                int m = m0 + wm*64 + mi*16 + g + half*8;
                float x = a[half*2], y = a[half*2 + 1];
                if (MODE == 0){
                    *(float2*)(g_fine_cal + (size_t)m*256 + col) = make_float2(x, y);
                    *(uint32_t*)(g_cat_hi + (size_t)m*512 + col) = packh2(x, y);
                } else if (MODE == 2){
                    if (col < OMC)
                        *(float2*)(g_om + (size_t)m*OMC + col) =
                            make_float2(x + bias[col], y + bias[col + 1]);
                } else {
                    float2 fc = *(const float2*)(g_fine_cal + (size_t)m*256 + col);
                    float2 o;
                    o.x = fmaxf(x + bias[col],     0.f) + fc.x;
                    o.y = fmaxf(y + bias[col + 1], 0.f) + fc.y;
                    *(float2*)(outp + (size_t)m*256 + col) = o;
                }
            }
        }
    }
}

// -------- deformable sampling: 1 warp = 1 pixel, uint2 gathers from cat_hi -------
__global__ __launch_bounds__(256)
void dcn_sample(){
    __shared__ float oms[8*OMC];
    int tid = threadIdx.x;
    int pixBase = blockIdx.x * 8;
    for (int i = tid; i < 8*OMC; i += 256)
        oms[i] = g_om[(size_t)pixBase*OMC + i];
    __syncthreads();

    int wid = tid >> 5, lane = tid & 31;
    int g4 = lane >> 3, l8 = lane & 7;
    int m = pixBase + wid;
    int b = m >> 12, rem = m & 4095, y = rem >> 6, x = rem & 63;
    const float* om = oms + wid*OMC;
    __half* colB = g_cols_hi + (size_t)m*KDCN;

    #pragma unroll
    for (int t = 0; t < 9; t++){
        int tyo = t/3 - 1, txo = t - (t/3)*3 - 1;
        #pragma unroll
        for (int gp = 0; gp < 2; gp++){
            int g = gp*4 + g4;
            float dy = om[g*18 + t*2];
            float dx = om[g*18 + t*2 + 1];
            float mk = 1.f / (1.f + __expf(-om[144 + g*9 + t]));  // (2*sig)*0.5
            float py = (float)(y + tyo) + dy;
            float px = (float)(x + txo) + dx;
            float y0f = floorf(py), x0f = floorf(px);
            float wy1 = py - y0f, wx1 = px - x0f;
            float wy0 = 1.f - wy1, wx0 = 1.f - wx1;
            int y0 = (int)y0f, x0 = (int)x0f;
            bool yin0 = ((unsigned)y0 < 64u), yin1 = ((unsigned)(y0+1) < 64u);
            bool xin0 = ((unsigned)x0 < 64u), xin1 = ((unsigned)(x0+1) < 64u);
            float w00 = mk*wy0*wx0, w01 = mk*wy0*wx1;
            float w10 = mk*wy1*wx0, w11 = mk*wy1*wx1;
            const __half* base = g_cat_hi + (size_t)(b << 12)*512 + 256 + g*32 + l8*4;
            int i00 = (y0*64 + x0)*512;
            float a0 = 0.f, a1 = 0.f, a2 = 0.f, a3 = 0.f;
            auto acc4 = [&](int off, float w){
                uint2 u = *(const uint2*)(base + off);
                float2 p0 = __half22float2(*(__half2*)&u.x);
                float2 p1 = __half22float2(*(__half2*)&u.y);
                a0 += w*p0.x; a1 += w*p0.y; a2 += w*p1.x; a3 += w*p1.y;
            };
            if (yin0 && xin0) acc4(i00,             w00);
            if (yin0 && xin1) acc4(i00 + 512,       w01);
            if (yin1 && xin0) acc4(i00 + 32768,     w10);
            if (yin1 && xin1) acc4(i00 + 33280,     w11);
            __half2 h0 = __floats2half2_rn(a0, a1);
            __half2 h1 = __floats2half2_rn(a2, a3);
            uint2 o;
            o.x = *(uint32_t*)&h0;
            o.y = *(uint32_t*)&h1;
            *(uint2*)(colB + t*256 + g*32 + l8*4) = o;
        }
    }
}

// ---------------- launcher -------------------------------------------------------
extern "C" void kernel_launch(void* const* d_in, const int* in_sizes, int n_in,
                              void* d_out, int out_size){
    const float* fine      = (const float*)d_in[0];
    const float* coarse    = (const float*)d_in[1];
    const float* fs_attn_w = (const float*)d_in[2];
    const float* fs_conv_w = (const float*)d_in[3];
    const float* offset_w  = (const float*)d_in[4];
    const float* om_w      = (const float*)d_in[5];
    const float* om_b      = (const float*)d_in[6];
    const float* dcn_w     = (const float*)d_in[7];
    const float* dcn_b     = (const float*)d_in[8];
    float* out = (float*)d_out;
    (void)in_sizes; (void)n_in; (void)out_size;

    const int GSM = 65536;    // 2 stages x (AH,BH) x 16KB -> 3 CTAs/SM
    const int WSM = 98304;    // wcomb: 2 stages x (AH,AL,BH) x 16KB
    cudaFuncSetAttribute(mmagemm<0>, cudaFuncAttributeMaxDynamicSharedMemorySize, GSM);
    cudaFuncSetAttribute(mmagemm<2>, cudaFuncAttributeMaxDynamicSharedMemorySize, GSM);
    cudaFuncSetAttribute(mmagemm<3>, cudaFuncAttributeMaxDynamicSharedMemorySize, GSM);
    cudaFuncSetAttribute(wcomb_attn, cudaFuncAttributeMaxDynamicSharedMemorySize, WSM);

    wprep      <<<5680, 256>>>(fs_conv_w, dcn_w, offset_w, om_w, fine);
    wcomb_attn <<<76,   256, WSM>>>(fs_attn_w);
    prep_pix   <<<4096, 256>>>(fine, coarse);

    mmagemm<0> <<<dim3(128, 2), 256, GSM>>>(nullptr, nullptr);
    mmagemm<2> <<<dim3(128, 2), 256, GSM>>>(om_b,   nullptr);
    dcn_sample <<<2048, 256>>>();
    mmagemm<3> <<<dim3(128, 2), 256, GSM>>>(dcn_b,  out);
}

// round 16
// speedup vs baseline: 1.1360x; 1.0001x over previous
#include <cuda_runtime.h>
#include <cuda_fp16.h>
#include <math.h>
#include <stdint.h>

#define B_   4
#define NPIX 16384
#define OMC  216
#define KDCN 2304

// ---------------- scratch (device globals) -----------------------------------
__device__ float g_part[32*B_*256];
__device__ float g_scale[B_*256];
__device__ float g_fine_cal[NPIX*256];
__device__ float g_om[NPIX*OMC];

__device__ __half g_fs_h[NPIX*256];                  // mode0 A (fp16)
__device__ __half g_cat_hi[NPIX*512];                // mode2 A (fp16); cols 256.. = 2*coarse_up
__device__ __half g_cols_hi[(size_t)NPIX*KDCN];      // mode3 A (fp16)

// weights
__device__ __half g_bt0h[256*256];                   // fs_conv_w^T fp16
__device__ __half g_bt2h[256*4608];                  // Wcomb^T fp16 (pad n 216->256)
__device__ __half g_bt3h[256*2304];                  // dcn_kernel^T fp16
__device__ __half g_ow_h[512*512], g_ow_l[512*512];  // offset_w split [c][f]
__device__ __half g_omt[9*256*512];                  // om_w^T fp16 [tap][n(pad)][f]

// ---------------- helpers ------------------------------------------------------
static __device__ __forceinline__ uint32_t smem_u32(const void* p){
    uint32_t a;
    asm("{ .reg .u64 t; cvta.to.shared.u64 t, %1; cvt.u32.u64 %0, t; }" : "=r"(a) : "l"(p));
    return a;
}
static __device__ __forceinline__ void cpa16(uint32_t dst, const void* src, int pbytes){
    asm volatile("cp.async.ca.shared.global [%0], [%1], 16, %2;"
                 :: "r"(dst), "l"(src), "r"(pbytes));
}
#define CP_COMMIT  asm volatile("cp.async.commit_group;" ::: "memory")
#define CP_WAIT1   asm volatile("cp.async.wait_group 1;" ::: "memory")
#define CP_WAIT0   asm volatile("cp.async.wait_group 0;" ::: "memory")
#define LDSM_X4(r, a) \
    asm volatile("ldmatrix.sync.aligned.m8n8.x4.shared.b16 {%0,%1,%2,%3}, [%4];" \
        : "=r"((r)[0]),"=r"((r)[1]),"=r"((r)[2]),"=r"((r)[3]) : "r"(a))
#define MMA16816(d, a, b0, b1) \
    asm volatile("mma.sync.aligned.m16n8k16.row.col.f32.f16.f16.f32 " \
        "{%0,%1,%2,%3}, {%4,%5,%6,%7}, {%8,%9}, {%0,%1,%2,%3};" \
        : "+f"((d)[0]),"+f"((d)[1]),"+f"((d)[2]),"+f"((d)[3]) \
        : "r"((a)[0]),"r"((a)[1]),"r"((a)[2]),"r"((a)[3]), "r"(b0), "r"(b1))

static __device__ __forceinline__ void split2(float v, __half& h, __half& l){
    h = __float2half_rn(v);
    l = __float2half_rn(v - __half2float(h));
}
static __device__ __forceinline__ uint32_t packh2(float x, float y){
    __half hx = __float2half_rn(x), hy = __float2half_rn(y);
    return (uint32_t)__half_as_ushort(hx) | ((uint32_t)__half_as_ushort(hy) << 16);
}

// ---------------- prep: pixel-side (needs g_scale) -------------------------------
__global__ void prep_pix(const float* __restrict__ fine, const float* __restrict__ coarse){
    int t = threadIdx.x;
    int m = blockIdx.x*4 + (t >> 6);
    int c = (t & 63)*4;
    int b = m >> 12, rem = m & 4095, y = rem >> 6, x = rem & 63;
    float fy = 0.5f*y - 0.25f, fx = 0.5f*x - 0.25f;
    float y0f = floorf(fy), x0f = floorf(fx);
    float wy1 = fy - y0f, wx1 = fx - x0f, wy0 = 1.f - wy1, wx0 = 1.f - wx1;
    int y0 = (int)y0f, x0 = (int)x0f;
    int y0c = min(max(y0,0),31), y1c = min(max(y0+1,0),31);
    int x0c = min(max(x0,0),31), x1c = min(max(x0+1,0),31);
    const float* cb = coarse + (size_t)(b*1024)*256 + c;
    float4 v00 = *(const float4*)(cb + (size_t)(y0c*32+x0c)*256);
    float4 v01 = *(const float4*)(cb + (size_t)(y0c*32+x1c)*256);
    float4 v10 = *(const float4*)(cb + (size_t)(y1c*32+x0c)*256);
    float4 v11 = *(const float4*)(cb + (size_t)(y1c*32+x1c)*256);
    float w00 = wy0*wx0, w01 = wy0*wx1, w10 = wy1*wx0, w11 = wy1*wx1;
    float4 v;
    v.x = w00*v00.x + w01*v01.x + w10*v10.x + w11*v11.x;
    v.y = w00*v00.y + w01*v01.y + w10*v10.y + w11*v11.y;
    v.z = w00*v00.z + w01*v01.z + w10*v10.z + w11*v11.z;
    v.w = w00*v00.w + w01*v01.w + w10*v10.w + w11*v11.w;
    uint2 co;
    co.x = packh2(2.f*v.x, 2.f*v.y);
    co.y = packh2(2.f*v.z, 2.f*v.w);
    *(uint2*)(g_cat_hi + (size_t)m*512 + 256 + c) = co;
    float4 f4 = *(const float4*)(fine + (size_t)m*256 + c);
    float4 s4 = *(const float4*)(g_scale + b*256 + c);
    uint2 fo;
    fo.x = packh2(f4.x*s4.x, f4.y*s4.y);
    fo.y = packh2(f4.z*s4.z, f4.w*s4.w);
    *(uint2*)(g_fs_h + (size_t)m*256 + c) = fo;
}

// ---- launch 1: weight prep + GAP partials (all independent) ----------------------
__global__ void wprep(const float* __restrict__ fs_conv_w,
                      const float* __restrict__ dcn_w,
                      const float* __restrict__ offw,
                      const float* __restrict__ omw,
                      const float* __restrict__ fine){
    __shared__ float tile[32][33];
    int blk = blockIdx.x;
    if (blk < 640){
        const float* W = (blk < 64) ? fs_conv_w : dcn_w;
        __half* T      = (blk < 64) ? g_bt0h    : g_bt3h;
        int KROWS      = (blk < 64) ? 256       : 2304;
        int b = (blk < 64) ? blk : blk - 64;
        int k0 = (b >> 3)*32, n0 = (b & 7)*32;
        int tx = threadIdx.x & 31, ty = threadIdx.x >> 5;
        #pragma unroll
        for (int i = 0; i < 4; i++)
            tile[ty + i*8][tx] = W[(size_t)(k0 + ty + i*8)*256 + n0 + tx];
        __syncthreads();
        #pragma unroll
        for (int i = 0; i < 4; i++)
            T[(size_t)(n0 + ty + i*8)*KROWS + k0 + tx] = __float2half_rn(tile[tx][ty + i*8]);
    } else if (blk < 1664){
        int i = (blk - 640)*256 + threadIdx.x;
        __half h, l; split2(offw[i], h, l);
        g_ow_h[i] = h; g_ow_l[i] = l;
    } else if (blk < 5552){
        int b = blk - 1664;
        int f = (b & 1)*256 + threadIdx.x;
        int n = (b >> 1) % 216;
        int tap = b / 432;
        g_omt[((size_t)tap*256 + n)*512 + f] =
            __float2half_rn(omw[((size_t)tap*512 + f)*216 + n]);
    } else {
        int gb = blk - 5552;                 // gap_partial
        int b = gb >> 5, chunk = gb & 31, c = threadIdx.x;
        const float* p = fine + ((size_t)(b*4096 + chunk*128))*256 + c;
        float s = 0.f;
        #pragma unroll 8
        for (int r = 0; r < 128; r++) s += p[(size_t)r*256];
        g_part[gb*256 + c] = s;
    }
}

// ---- launch 2: Wcomb HMMA (blocks 0..71) + attention scale (72..75) --------------
__global__ void __launch_bounds__(256)
wcomb_attn(const float* __restrict__ attn_w){
    if (blockIdx.x >= 72){
        __shared__ float gp[256];
        int b = blockIdx.x - 72, t = threadIdx.x;
        float s = 0.f;
        #pragma unroll
        for (int ch = 0; ch < 32; ch++) s += g_part[(b*32 + ch)*256 + t];
        gp[t] = s * (1.f/4096.f);
        __syncthreads();
        float acc = 0.f;
        for (int c = 0; c < 256; c++) acc += gp[c] * attn_w[c*256 + t];
        g_scale[b*256 + t] = 1.f + 1.f/(1.f + expf(-acc));
        return;
    }
    constexpr int Kk = 512, NC = 8;
    extern __shared__ __align__(16) char smem[];
    uint32_t sb = smem_u32(smem);
    int tid = threadIdx.x, lane = tid & 31, wid = tid >> 5;
    int blk = blockIdx.x;
    int tap = blk >> 3;
    int r8  = blk & 7;
    int m0 = (r8 >> 1)*128, n0 = (r8 & 1)*128;
    int wm = wid >> 2, wn = wid & 3;
    const bool act = (n0 + wn*32 < OMC);
    const __half* Bh = g_omt + (size_t)tap*256*512;

    auto load_chunk = [&](int stage, int k0){
        uint32_t base = sb + stage*49152;
        #pragma unroll
        for (int u = 0; u < 4; u++){
            int idx = tid + u*256;
            int row = idx >> 3, ch = idx & 7;
            uint32_t d = base + (uint32_t)(row*128 + ((ch ^ (row & 7)) << 4));
            size_t aoff = (size_t)(m0 + row)*Kk + k0 + ch*8;
            size_t boff = (size_t)(n0 + row)*Kk + k0 + ch*8;
            cpa16(d,         g_ow_h + aoff, 16);
            cpa16(d + 16384, g_ow_l + aoff, 16);
            cpa16(d + 32768, Bh + boff, 16);
        }
    };

    int rbase = wm*64 + ((lane >> 3) & 1)*8 + (lane & 7);
    int khA   = lane >> 4;
    int nbase = wn*32 + ((lane >> 4) & 1)*8 + (lane & 7);
    int khB   = (lane >> 3) & 1;
    uint32_t aswz = (uint32_t)(rbase & 7), bswz = (uint32_t)(nbase & 7);

    float acc[4][4][4];
    #pragma unroll
    for (int i = 0; i < 4; i++)
        #pragma unroll
        for (int j = 0; j < 4; j++)
            #pragma unroll
            for (int q = 0; q < 4; q++) acc[i][j][q] = 0.f;

    load_chunk(0, 0);
    CP_COMMIT;
    for (int c = 0; c < NC; c++){
        if (c + 1 < NC) load_chunk((c + 1) & 1, (c + 1)*64);
        CP_COMMIT;
        if (c + 1 < NC) CP_WAIT1; else CP_WAIT0;
        __syncthreads();
        if (act){
            uint32_t base = sb + (c & 1)*49152;
            #pragma unroll
            for (int ks = 0; ks < 4; ks++){
                uint32_t aH[4][4], aL[4][4], bH[2][4];
                #pragma unroll
                for (int mi = 0; mi < 4; mi++){
                    uint32_t off = base + (uint32_t)((rbase + mi*16)*128
                                 + ((((uint32_t)(ks*2 + khA)) ^ aswz) << 4));
                    LDSM_X4(aH[mi], off);
                    LDSM_X4(aL[mi], off + 16384);
                }
                #pragma unroll
                for (int nb = 0; nb < 2; nb++){
                    uint32_t off = base + 32768 + (uint32_t)((nbase + nb*16)*128
                                 + ((((uint32_t)(ks*2 + khB)) ^ bswz) << 4));
                    LDSM_X4(bH[nb], off);
                }
                #pragma unroll
                for (int mi = 0; mi < 4; mi++)
                    #pragma unroll
                    for (int nj = 0; nj < 4; nj++){
                        uint32_t h0 = bH[nj >> 1][(nj & 1)*2], h1 = bH[nj >> 1][(nj & 1)*2 + 1];
                        MMA16816(acc[mi][nj], aH[mi], h0, h1);
                        MMA16816(acc[mi][nj], aL[mi], h0, h1);
                    }
            }
        }
        __syncthreads();
    }

    int g = lane >> 2, th = lane & 3;
    #pragma unroll
    for (int mi = 0; mi < 4; mi++){
        #pragma unroll
        for (int nj = 0; nj < 4; nj++){
            int col = n0 + wn*32 + nj*8 + th*2;
            float* a = acc[mi][nj];
            #pragma unroll
            for (int half = 0; half < 2; half++){
                int m = m0 + wm*64 + mi*16 + g + half*8;
                if (col < OMC){
                    g_bt2h[(size_t)col*4608 + tap*512 + m]     = __float2half_rn(a[half*2]);
                    g_bt2h[(size_t)(col+1)*4608 + tap*512 + m] = __float2half_rn(a[half*2+1]);
                }
            }
        }
    }
}

// ------- warp-MMA GEMM, 1-term fp16, BM128 BN128 BK64, 2 CTAs/SM forced ---------
// MODE 0: fine_cal = fs_h @ bt0                (K=256)
// MODE 2: om = im2col(cat_hi) @ bt2 + bias      (K=4608, n<216; pad warps skip MMA)
// MODE 3: out = relu(cols_hi @ bt3 + b) + fc    (K=2304)
template<int MODE>
__global__ void __launch_bounds__(256, 2)
mmagemm(const float* __restrict__ bias, float* __restrict__ outp){
    constexpr int Kk = (MODE==0) ? 256 : (MODE==2) ? 4608 : 2304;
    constexpr int NC = Kk / 64;
    constexpr uint32_t STAGE = 32768;
    const __half* Ah = (MODE==0) ? g_fs_h : (MODE==2) ? g_cat_hi : g_cols_hi;
    const __half* Bh = (MODE==0) ? g_bt0h : (MODE==2) ? g_bt2h : g_bt3h;

    extern __shared__ __align__(16) char smem[];
    uint32_t sb = smem_u32(smem);
    int tid = threadIdx.x, lane = tid & 31, wid = tid >> 5;
    int m0 = blockIdx.x*128, n0 = blockIdx.y*128;
    int wm = wid >> 2, wn = wid & 3;
    const bool act = (MODE != 2) || (n0 + wn*32 < OMC);

    auto load_chunk = [&](int stage, int k0){
        uint32_t base = sb + stage*STAGE;
        #pragma unroll
        for (int u = 0; u < 4; u++){
            int idx = tid + u*256;
            int row = idx >> 3, ch = idx & 7;
            uint32_t d = base + (uint32_t)(row*128 + ((ch ^ (row & 7)) << 4));
            size_t boff = (size_t)(n0 + row)*Kk + k0 + ch*8;
            cpa16(d + 16384, Bh + boff, 16);
            if (MODE == 2){
                int m = m0 + row, bb = m >> 12, rem = m & 4095;
                int yy = rem >> 6, xx = rem & 63;
                int tap = k0 >> 9, cc = (k0 & 511) + ch*8;
                int ny = yy + tap/3 - 1, nx = xx + tap%3 - 1;
                bool ok = ((unsigned)ny < 64u) && ((unsigned)nx < 64u);
                size_t aoff = ok ? ((size_t)((bb << 12) + ny*64 + nx)*512 + cc) : 0;
                cpa16(d, Ah + aoff, ok ? 16 : 0);
            } else {
                size_t aoff = (size_t)(m0 + row)*Kk + k0 + ch*8;
                cpa16(d, Ah + aoff, 16);
            }
        }
    };

    int rbase = wm*64 + ((lane >> 3) & 1)*8 + (lane & 7);
    int khA   = lane >> 4;
    int nbase = wn*32 + ((lane >> 4) & 1)*8 + (lane & 7);
    int khB   = (lane >> 3) & 1;
    uint32_t aswz = (uint32_t)(rbase & 7), bswz = (uint32_t)(nbase & 7);

    float acc[4][4][4];
    #pragma unroll
    for (int i = 0; i < 4; i++)
        #pragma unroll
        for (int j = 0; j < 4; j++)
            #pragma unroll
            for (int q = 0; q < 4; q++) acc[i][j][q] = 0.f;

    load_chunk(0, 0);
    CP_COMMIT;
    for (int c = 0; c < NC; c++){
        if (c + 1 < NC) load_chunk((c + 1) & 1, (c + 1)*64);
        CP_COMMIT;
        if (c + 1 < NC) CP_WAIT1; else CP_WAIT0;
        __syncthreads();
        if (act){
            uint32_t base = sb + (c & 1)*STAGE;
            #pragma unroll
            for (int ks = 0; ks < 4; ks++){
                uint32_t aH[4][4], bH[2][4];
                #pragma unroll
                for (int mi = 0; mi < 4; mi++){
                    uint32_t off = base + (uint32_t)((rbase + mi*16)*128
                                 + ((((uint32_t)(ks*2 + khA)) ^ aswz) << 4));
                    LDSM_X4(aH[mi], off);
                }
                #pragma unroll
                for (int nb = 0; nb < 2; nb++){
                    uint32_t off = base + 16384 + (uint32_t)((nbase + nb*16)*128
                                 + ((((uint32_t)(ks*2 + khB)) ^ bswz) << 4));
                    LDSM_X4(bH[nb], off);
                }
                #pragma unroll
                for (int mi = 0; mi < 4; mi++)
                    #pragma unroll
                    for (int nj = 0; nj < 4; nj++){
                        uint32_t h0 = bH[nj >> 1][(nj & 1)*2], h1 = bH[nj >> 1][(nj & 1)*2 + 1];
                        MMA16816(acc[mi][nj], aH[mi], h0, h1);
                    }
            }
        }
        __syncthreads();
    }

    if (!act) return;
    int g = lane >> 2, th = lane & 3;
    #pragma unroll
    for (int mi = 0; mi < 4; mi++){
        #pragma unroll
        for (int nj = 0; nj < 4; nj++){
            int col = n0 + wn*32 + nj*8 + th*2;
            float* a = acc[mi][nj];
            #pragma unroll
            for (int half = 0; half < 2; half++){
                int m = m0 + wm*64 + mi*16 + g + half*8;
                float x = a[half*2], y = a[half*2 + 1];
                if (MODE == 0){
                    *(float2*)(g_fine_cal + (size_t)m*256 + col) = make_float2(x, y);
                    *(uint32_t*)(g_cat_hi + (size_t)m*512 + col) = packh2(x, y);
                } else if (MODE == 2){
                    if (col < OMC)
                        *(float2*)(g_om + (size_t)m*OMC + col) =
                            make_float2(x + bias[col], y + bias[col + 1]);
                } else {
                    float2 fc = *(const float2*)(g_fine_cal + (size_t)m*256 + col);
                    float2 o;
                    o.x = fmaxf(x + bias[col],     0.f) + fc.x;
                    o.y = fmaxf(y + bias[col + 1], 0.f) + fc.y;
                    *(float2*)(outp + (size_t)m*256 + col) = o;
                }
            }
        }
    }
}

// -------- deformable sampling: 1 warp = 1 pixel, uint2 gathers from cat_hi -------
__global__ __launch_bounds__(256)
void dcn_sample(){
    __shared__ float oms[8*OMC];
    int tid = threadIdx.x;
    int pixBase = blockIdx.x * 8;
    for (int i = tid; i < 8*OMC; i += 256)
        oms[i] = g_om[(size_t)pixBase*OMC + i];
    __syncthreads();

    int wid = tid >> 5, lane = tid & 31;
    int g4 = lane >> 3, l8 = lane & 7;
    int m = pixBase + wid;
    int b = m >> 12, rem = m & 4095, y = rem >> 6, x = rem & 63;
    const float* om = oms + wid*OMC;
    __half* colB = g_cols_hi + (size_t)m*KDCN;

    #pragma unroll
    for (int t = 0; t < 9; t++){
        int tyo = t/3 - 1, txo = t - (t/3)*3 - 1;
        #pragma unroll
        for (int gp = 0; gp < 2; gp++){
            int g = gp*4 + g4;
            float dy = om[g*18 + t*2];
            float dx = om[g*18 + t*2 + 1];
            float mk = 1.f / (1.f + __expf(-om[144 + g*9 + t]));  // (2*sig)*0.5
            float py = (float)(y + tyo) + dy;
            float px = (float)(x + txo) + dx;
            float y0f = floorf(py), x0f = floorf(px);
            float wy1 = py - y0f, wx1 = px - x0f;
            float wy0 = 1.f - wy1, wx0 = 1.f - wx1;
            int y0 = (int)y0f, x0 = (int)x0f;
            bool yin0 = ((unsigned)y0 < 64u), yin1 = ((unsigned)(y0+1) < 64u);
            bool xin0 = ((unsigned)x0 < 64u), xin1 = ((unsigned)(x0+1) < 64u);
            float w00 = mk*wy0*wx0, w01 = mk*wy0*wx1;
            float w10 = mk*wy1*wx0, w11 = mk*wy1*wx1;
            const __half* base = g_cat_hi + (size_t)(b << 12)*512 + 256 + g*32 + l8*4;
            int i00 = (y0*64 + x0)*512;
            float a0 = 0.f, a1 = 0.f, a2 = 0.f, a3 = 0.f;
            auto acc4 = [&](int off, float w){
                uint2 u = *(const uint2*)(base + off);
                float2 p0 = __half22float2(*(__half2*)&u.x);
                float2 p1 = __half22float2(*(__half2*)&u.y);
                a0 += w*p0.x; a1 += w*p0.y; a2 += w*p1.x; a3 += w*p1.y;
            };
            if (yin0 && xin0) acc4(i00,             w00);
            if (yin0 && xin1) acc4(i00 + 512,       w01);
            if (yin1 && xin0) acc4(i00 + 32768,     w10);
            if (yin1 && xin1) acc4(i00 + 33280,     w11);
            __half2 h0 = __floats2half2_rn(a0, a1);
            __half2 h1 = __floats2half2_rn(a2, a3);
            uint2 o;
            o.x = *(uint32_t*)&h0;
            o.y = *(uint32_t*)&h1;
            *(uint2*)(colB + t*256 + g*32 + l8*4) = o;
        }
    }
}

// ---------------- launcher -------------------------------------------------------
extern "C" void kernel_launch(void* const* d_in, const int* in_sizes, int n_in,
                              void* d_out, int out_size){
    const float* fine      = (const float*)d_in[0];
    const float* coarse    = (const float*)d_in[1];
    const float* fs_attn_w = (const float*)d_in[2];
    const float* fs_conv_w = (const float*)d_in[3];
    const float* offset_w  = (const float*)d_in[4];
    const float* om_w      = (const float*)d_in[5];
    const float* om_b      = (const float*)d_in[6];
    const float* dcn_w     = (const float*)d_in[7];
    const float* dcn_b     = (const float*)d_in[8];
    float* out = (float*)d_out;
    (void)in_sizes; (void)n_in; (void)out_size;

    const int GSM = 65536;    // 2 stages x (AH,BH) x 16KB
    const int WSM = 98304;    // wcomb: 2 stages x (AH,AL,BH) x 16KB
    cudaFuncSetAttribute(mmagemm<0>, cudaFuncAttributeMaxDynamicSharedMemorySize, GSM);
    cudaFuncSetAttribute(mmagemm<2>, cudaFuncAttributeMaxDynamicSharedMemorySize, GSM);
    cudaFuncSetAttribute(mmagemm<3>, cudaFuncAttributeMaxDynamicSharedMemorySize, GSM);
    cudaFuncSetAttribute(wcomb_attn, cudaFuncAttributeMaxDynamicSharedMemorySize, WSM);

    wprep      <<<5680, 256>>>(fs_conv_w, dcn_w, offset_w, om_w, fine);
    wcomb_attn <<<76,   256, WSM>>>(fs_attn_w);
    prep_pix   <<<4096, 256>>>(fine, coarse);

    mmagemm<0> <<<dim3(128, 2), 256, GSM>>>(nullptr, nullptr);
    mmagemm<2> <<<dim3(128, 2), 256, GSM>>>(om_b,   nullptr);
    dcn_sample <<<2048, 256>>>();
    mmagemm<3> <<<dim3(128, 2), 256, GSM>>>(dcn_b,  out);
}

// round 17
// speedup vs baseline: 1.1463x; 1.0091x over previous
#include <cuda_runtime.h>
#include <cuda_fp16.h>
#include <math.h>
#include <stdint.h>

#define B_   4
#define NPIX 16384
#define OMC  216
#define KDCN 2304

// ---------------- scratch (device globals) -----------------------------------
__device__ float g_part[32*B_*256];
__device__ float g_scale[B_*256];
__device__ float g_fine_cal[NPIX*256];
__device__ float g_om[NPIX*OMC];

__device__ __half g_cat_hi[NPIX*512];                // mode2 A; cols 256.. = 2*coarse_up
__device__ __half g_cols_hi[(size_t)NPIX*KDCN];      // mode3 A

// weights
__device__ __half g_bt0h[256*256];                   // fs_conv_w^T fp16
__device__ __half g_bt2h[256*4608];                  // Wcomb^T fp16 (pad n 216->256)
__device__ __half g_bt3h[256*2304];                  // dcn_kernel^T fp16
__device__ __half g_ow_h[512*512], g_ow_l[512*512];  // offset_w split [c][f]
__device__ __half g_omt[9*256*512];                  // om_w^T fp16 [tap][n(pad)][f]

// ---------------- helpers ------------------------------------------------------
static __device__ __forceinline__ uint32_t smem_u32(const void* p){
    uint32_t a;
    asm("{ .reg .u64 t; cvta.to.shared.u64 t, %1; cvt.u32.u64 %0, t; }" : "=r"(a) : "l"(p));
    return a;
}
static __device__ __forceinline__ void cpa16(uint32_t dst, const void* src, int pbytes){
    asm volatile("cp.async.ca.shared.global [%0], [%1], 16, %2;"
                 :: "r"(dst), "l"(src), "r"(pbytes));
}
#define CP_COMMIT  asm volatile("cp.async.commit_group;" ::: "memory")
#define CP_WAIT1   asm volatile("cp.async.wait_group 1;" ::: "memory")
#define CP_WAIT0   asm volatile("cp.async.wait_group 0;" ::: "memory")
#define LDSM_X4(r, a) \
    asm volatile("ldmatrix.sync.aligned.m8n8.x4.shared.b16 {%0,%1,%2,%3}, [%4];" \
        : "=r"((r)[0]),"=r"((r)[1]),"=r"((r)[2]),"=r"((r)[3]) : "r"(a))
#define MMA16816(d, a, b0, b1) \
    asm volatile("mma.sync.aligned.m16n8k16.row.col.f32.f16.f16.f32 " \
        "{%0,%1,%2,%3}, {%4,%5,%6,%7}, {%8,%9}, {%0,%1,%2,%3};" \
        : "+f"((d)[0]),"+f"((d)[1]),"+f"((d)[2]),"+f"((d)[3]) \
        : "r"((a)[0]),"r"((a)[1]),"r"((a)[2]),"r"((a)[3]), "r"(b0), "r"(b1))

static __device__ __forceinline__ void split2(float v, __half& h, __half& l){
    h = __float2half_rn(v);
    l = __float2half_rn(v - __half2float(h));
}
static __device__ __forceinline__ uint32_t packh2(float x, float y){
    __half hx = __float2half_rn(x), hy = __float2half_rn(y);
    return (uint32_t)__half_as_ushort(hx) | ((uint32_t)__half_as_ushort(hy) << 16);
}

// ---- launch 1: weight prep + GAP partials + coarse upsample (all independent) ----
// [0,64)    tr16 fs_conv_w      [64,640)    tr16 dcn_w
// [640,1664) owsplit offset_w   [1664,5552) omt transpose
// [5552,5680) gap_partial       [5680,9776) coarse 2x upsample -> cat_hi cols 256..
__global__ void wprep(const float* __restrict__ fs_conv_w,
                      const float* __restrict__ dcn_w,
                      const float* __restrict__ offw,
                      const float* __restrict__ omw,
                      const float* __restrict__ fine,
                      const float* __restrict__ coarse){
    __shared__ float tile[32][33];
    int blk = blockIdx.x;
    if (blk < 640){
        const float* W = (blk < 64) ? fs_conv_w : dcn_w;
        __half* T      = (blk < 64) ? g_bt0h    : g_bt3h;
        int KROWS      = (blk < 64) ? 256       : 2304;
        int b = (blk < 64) ? blk : blk - 64;
        int k0 = (b >> 3)*32, n0 = (b & 7)*32;
        int tx = threadIdx.x & 31, ty = threadIdx.x >> 5;
        #pragma unroll
        for (int i = 0; i < 4; i++)
            tile[ty + i*8][tx] = W[(size_t)(k0 + ty + i*8)*256 + n0 + tx];
        __syncthreads();
        #pragma unroll
        for (int i = 0; i < 4; i++)
            T[(size_t)(n0 + ty + i*8)*KROWS + k0 + tx] = __float2half_rn(tile[tx][ty + i*8]);
    } else if (blk < 1664){
        int i = (blk - 640)*256 + threadIdx.x;
        __half h, l; split2(offw[i], h, l);
        g_ow_h[i] = h; g_ow_l[i] = l;
    } else if (blk < 5552){
        int b = blk - 1664;
        int f = (b & 1)*256 + threadIdx.x;
        int n = (b >> 1) % 216;
        int tap = b / 432;
        g_omt[((size_t)tap*256 + n)*512 + f] =
            __float2half_rn(omw[((size_t)tap*512 + f)*216 + n]);
    } else if (blk < 5680){
        int gb = blk - 5552;                 // gap_partial
        int b = gb >> 5, chunk = gb & 31, c = threadIdx.x;
        const float* p = fine + ((size_t)(b*4096 + chunk*128))*256 + c;
        float s = 0.f;
        #pragma unroll 8
        for (int r = 0; r < 128; r++) s += p[(size_t)r*256];
        g_part[gb*256 + c] = s;
    } else {
        int t = threadIdx.x;                 // upsample: 4 pixels/block, 4ch/thread
        int m = (blk - 5680)*4 + (t >> 6);
        int c = (t & 63)*4;
        int b = m >> 12, rem = m & 4095, y = rem >> 6, x = rem & 63;
        float fy = 0.5f*y - 0.25f, fx = 0.5f*x - 0.25f;
        float y0f = floorf(fy), x0f = floorf(fx);
        float wy1 = fy - y0f, wx1 = fx - x0f, wy0 = 1.f - wy1, wx0 = 1.f - wx1;
        int y0 = (int)y0f, x0 = (int)x0f;
        int y0c = min(max(y0,0),31), y1c = min(max(y0+1,0),31);
        int x0c = min(max(x0,0),31), x1c = min(max(x0+1,0),31);
        const float* cb = coarse + (size_t)(b*1024)*256 + c;
        float4 v00 = *(const float4*)(cb + (size_t)(y0c*32+x0c)*256);
        float4 v01 = *(const float4*)(cb + (size_t)(y0c*32+x1c)*256);
        float4 v10 = *(const float4*)(cb + (size_t)(y1c*32+x0c)*256);
        float4 v11 = *(const float4*)(cb + (size_t)(y1c*32+x1c)*256);
        float w00 = wy0*wx0, w01 = wy0*wx1, w10 = wy1*wx0, w11 = wy1*wx1;
        float4 v;
        v.x = w00*v00.x + w01*v01.x + w10*v10.x + w11*v11.x;
        v.y = w00*v00.y + w01*v01.y + w10*v10.y + w11*v11.y;
        v.z = w00*v00.z + w01*v01.z + w10*v10.z + w11*v11.z;
        v.w = w00*v00.w + w01*v01.w + w10*v10.w + w11*v11.w;
        uint2 co;
        co.x = packh2(2.f*v.x, 2.f*v.y);
        co.y = packh2(2.f*v.z, 2.f*v.w);
        *(uint2*)(g_cat_hi + (size_t)m*512 + 256 + c) = co;
    }
}

// ---- launch 2: Wcomb HMMA (blocks 0..71) + attention scale (72..75) --------------
__global__ void __launch_bounds__(256)
wcomb_attn(const float* __restrict__ attn_w){
    if (blockIdx.x >= 72){
        __shared__ float gp[256];
        int b = blockIdx.x - 72, t = threadIdx.x;
        float s = 0.f;
        #pragma unroll
        for (int ch = 0; ch < 32; ch++) s += g_part[(b*32 + ch)*256 + t];
        gp[t] = s * (1.f/4096.f);
        __syncthreads();
        float acc = 0.f;
        for (int c = 0; c < 256; c++) acc += gp[c] * attn_w[c*256 + t];
        g_scale[b*256 + t] = 1.f + 1.f/(1.f + expf(-acc));
        return;
    }
    constexpr int Kk = 512, NC = 8;
    extern __shared__ __align__(16) char smem[];
    uint32_t sb = smem_u32(smem);
    int tid = threadIdx.x, lane = tid & 31, wid = tid >> 5;
    int blk = blockIdx.x;
    int tap = blk >> 3;
    int r8  = blk & 7;
    int m0 = (r8 >> 1)*128, n0 = (r8 & 1)*128;
    int wm = wid >> 2, wn = wid & 3;
    const bool act = (n0 + wn*32 < OMC);
    const __half* Bh = g_omt + (size_t)tap*256*512;

    auto load_chunk = [&](int stage, int k0){
        uint32_t base = sb + stage*49152;
        #pragma unroll
        for (int u = 0; u < 4; u++){
            int idx = tid + u*256;
            int row = idx >> 3, ch = idx & 7;
            uint32_t d = base + (uint32_t)(row*128 + ((ch ^ (row & 7)) << 4));
            size_t aoff = (size_t)(m0 + row)*Kk + k0 + ch*8;
            size_t boff = (size_t)(n0 + row)*Kk + k0 + ch*8;
            cpa16(d,         g_ow_h + aoff, 16);
            cpa16(d + 16384, g_ow_l + aoff, 16);
            cpa16(d + 32768, Bh + boff, 16);
        }
    };

    int rbase = wm*64 + ((lane >> 3) & 1)*8 + (lane & 7);
    int khA   = lane >> 4;
    int nbase = wn*32 + ((lane >> 4) & 1)*8 + (lane & 7);
    int khB   = (lane >> 3) & 1;
    uint32_t aswz = (uint32_t)(rbase & 7), bswz = (uint32_t)(nbase & 7);

    float acc[4][4][4];
    #pragma unroll
    for (int i = 0; i < 4; i++)
        #pragma unroll
        for (int j = 0; j < 4; j++)
            #pragma unroll
            for (int q = 0; q < 4; q++) acc[i][j][q] = 0.f;

    load_chunk(0, 0);
    CP_COMMIT;
    for (int c = 0; c < NC; c++){
        if (c + 1 < NC) load_chunk((c + 1) & 1, (c + 1)*64);
        CP_COMMIT;
        if (c + 1 < NC) CP_WAIT1; else CP_WAIT0;
        __syncthreads();
        if (act){
            uint32_t base = sb + (c & 1)*49152;
            #pragma unroll
            for (int ks = 0; ks < 4; ks++){
                uint32_t aH[4][4], aL[4][4], bH[2][4];
                #pragma unroll
                for (int mi = 0; mi < 4; mi++){
                    uint32_t off = base + (uint32_t)((rbase + mi*16)*128
                                 + ((((uint32_t)(ks*2 + khA)) ^ aswz) << 4));
                    LDSM_X4(aH[mi], off);
                    LDSM_X4(aL[mi], off + 16384);
                }
                #pragma unroll
                for (int nb = 0; nb < 2; nb++){
                    uint32_t off = base + 32768 + (uint32_t)((nbase + nb*16)*128
                                 + ((((uint32_t)(ks*2 + khB)) ^ bswz) << 4));
                    LDSM_X4(bH[nb], off);
                }
                #pragma unroll
                for (int mi = 0; mi < 4; mi++)
                    #pragma unroll
                    for (int nj = 0; nj < 4; nj++){
                        uint32_t h0 = bH[nj >> 1][(nj & 1)*2], h1 = bH[nj >> 1][(nj & 1)*2 + 1];
                        MMA16816(acc[mi][nj], aH[mi], h0, h1);
                        MMA16816(acc[mi][nj], aL[mi], h0, h1);
                    }
            }
        }
        __syncthreads();
    }

    int g = lane >> 2, th = lane & 3;
    #pragma unroll
    for (int mi = 0; mi < 4; mi++){
        #pragma unroll
        for (int nj = 0; nj < 4; nj++){
            int col = n0 + wn*32 + nj*8 + th*2;
            float* a = acc[mi][nj];
            #pragma unroll
            for (int half = 0; half < 2; half++){
                int m = m0 + wm*64 + mi*16 + g + half*8;
                if (col < OMC){
                    g_bt2h[(size_t)col*4608 + tap*512 + m]     = __float2half_rn(a[half*2]);
                    g_bt2h[(size_t)(col+1)*4608 + tap*512 + m] = __float2half_rn(a[half*2+1]);
                }
            }
        }
    }
}

// ------- warp-MMA GEMM, 1-term fp16, BM128 BN128 BK64 ---------------------------
// MODE 0: fine_cal = (fine .* scale) @ bt0     (K=256; A built in-kernel: LDG+STS)
// MODE 2: om = im2col(cat_hi) @ bt2 + bias      (K=4608, n<216; pad warps skip MMA)
// MODE 3: out = relu(cols_hi @ bt3 + b) + fc    (K=2304)
template<int MODE>
__global__ void __launch_bounds__(256, 2)
mmagemm(const float* __restrict__ bias, float* __restrict__ outp,
        const float* __restrict__ fineA){
    constexpr int Kk = (MODE==0) ? 256 : (MODE==2) ? 4608 : 2304;
    constexpr int NC = Kk / 64;
    constexpr uint32_t STAGE = 32768;
    const __half* Ah = (MODE==2) ? g_cat_hi : g_cols_hi;   // unused for MODE 0
    const __half* Bh = (MODE==0) ? g_bt0h : (MODE==2) ? g_bt2h : g_bt3h;

    extern __shared__ __align__(16) char smem[];
    uint32_t sb = smem_u32(smem);
    int tid = threadIdx.x, lane = tid & 31, wid = tid >> 5;
    int m0 = blockIdx.x*128, n0 = blockIdx.y*128;
    int wm = wid >> 2, wn = wid & 3;
    const bool act = (MODE != 2) || (n0 + wn*32 < OMC);
    const float* scb = g_scale + ((m0 >> 12)*256);   // batch-constant per block

    auto load_chunk = [&](int stage, int k0){
        uint32_t base = sb + stage*STAGE;
        #pragma unroll
        for (int u = 0; u < 4; u++){
            int idx = tid + u*256;
            int row = idx >> 3, ch = idx & 7;
            uint32_t d = base + (uint32_t)(row*128 + ((ch ^ (row & 7)) << 4));
            size_t boff = (size_t)(n0 + row)*Kk + k0 + ch*8;
            cpa16(d + 16384, Bh + boff, 16);
            if (MODE == 2){
                int m = m0 + row, bb = m >> 12, rem = m & 4095;
                int yy = rem >> 6, xx = rem & 63;
                int tap = k0 >> 9, cc = (k0 & 511) + ch*8;
                int ny = yy + tap/3 - 1, nx = xx + tap%3 - 1;
                bool ok = ((unsigned)ny < 64u) && ((unsigned)nx < 64u);
                size_t aoff = ok ? ((size_t)((bb << 12) + ny*64 + nx)*512 + cc) : 0;
                cpa16(d, Ah + aoff, ok ? 16 : 0);
            } else if (MODE == 3){
                size_t aoff = (size_t)(m0 + row)*Kk + k0 + ch*8;
                cpa16(d, Ah + aoff, 16);
            } else {
                // MODE 0: A = fine .* scale, fp32 -> fp16, regular STS
                int k = k0 + ch*8;
                const float* fp = fineA + (size_t)(m0 + row)*256 + k;
                float4 f0 = *(const float4*)fp;
                float4 f1 = *(const float4*)(fp + 4);
                float4 s0 = *(const float4*)(scb + k);
                float4 s1 = *(const float4*)(scb + k + 4);
                uint4 v;
                v.x = packh2(f0.x*s0.x, f0.y*s0.y);
                v.y = packh2(f0.z*s0.z, f0.w*s0.w);
                v.z = packh2(f1.x*s1.x, f1.y*s1.y);
                v.w = packh2(f1.z*s1.z, f1.w*s1.w);
                *(uint4*)(smem + (d - sb)) = v;
            }
        }
    };

    int rbase = wm*64 + ((lane >> 3) & 1)*8 + (lane & 7);
    int khA   = lane >> 4;
    int nbase = wn*32 + ((lane >> 4) & 1)*8 + (lane & 7);
    int khB   = (lane >> 3) & 1;
    uint32_t aswz = (uint32_t)(rbase & 7), bswz = (uint32_t)(nbase & 7);

    float acc[4][4][4];
    #pragma unroll
    for (int i = 0; i < 4; i++)
        #pragma unroll
        for (int j = 0; j < 4; j++)
            #pragma unroll
            for (int q = 0; q < 4; q++) acc[i][j][q] = 0.f;

    load_chunk(0, 0);
    CP_COMMIT;
    for (int c = 0; c < NC; c++){
        if (c + 1 < NC) load_chunk((c + 1) & 1, (c + 1)*64);
        CP_COMMIT;
        if (c + 1 < NC) CP_WAIT1; else CP_WAIT0;
        __syncthreads();
        if (act){
            uint32_t base = sb + (c & 1)*STAGE;
            #pragma unroll
            for (int ks = 0; ks < 4; ks++){
                uint32_t aH[4][4], bH[2][4];
                #pragma unroll
                for (int mi = 0; mi < 4; mi++){
                    uint32_t off = base + (uint32_t)((rbase + mi*16)*128
                                 + ((((uint32_t)(ks*2 + khA)) ^ aswz) << 4));
                    LDSM_X4(aH[mi], off);
                }
                #pragma unroll
                for (int nb = 0; nb < 2; nb++){
                    uint32_t off = base + 16384 + (uint32_t)((nbase + nb*16)*128
                                 + ((((uint32_t)(ks*2 + khB)) ^ bswz) << 4));
                    LDSM_X4(bH[nb], off);
                }
                #pragma unroll
                for (int mi = 0; mi < 4; mi++)
                    #pragma unroll
                    for (int nj = 0; nj < 4; nj++){
                        uint32_t h0 = bH[nj >> 1][(nj & 1)*2], h1 = bH[nj >> 1][(nj & 1)*2 + 1];
                        MMA16816(acc[mi][nj], aH[mi], h0, h1);
                    }
            }
        }
        __syncthreads();
    }

    if (!act) return;
    int g = lane >> 2, th = lane & 3;
    #pragma unroll
    for (int mi = 0; mi < 4; mi++){
        #pragma unroll
        for (int nj = 0; nj < 4; nj++){
            int col = n0 + wn*32 + nj*8 + th*2;
            float* a = acc[mi][nj];
            #pragma unroll
            for (int half = 0; half < 2; half++){
                int m = m0 + wm*64 + mi*16 + g + half*8;
                float x = a[half*2], y = a[half*2 + 1];
                if (MODE == 0){
                    *(float2*)(g_fine_cal + (size_t)m*256 + col) = make_float2(x, y);
                    *(uint32_t*)(g_cat_hi + (size_t)m*512 + col) = packh2(x, y);
                } else if (MODE == 2){
                    if (col < OMC)
                        *(float2*)(g_om + (size_t)m*OMC + col) =
                            make_float2(x + bias[col], y + bias[col + 1]);
                } else {
                    float2 fc = *(const float2*)(g_fine_cal + (size_t)m*256 + col);
                    float2 o;
                    o.x = fmaxf(x + bias[col],     0.f) + fc.x;
                    o.y = fmaxf(y + bias[col + 1], 0.f) + fc.y;
                    *(float2*)(outp + (size_t)m*256 + col) = o;
                }
            }
        }
    }
}

// -------- deformable sampling: 1 warp = 1 pixel, uint2 gathers from cat_hi -------
__global__ __launch_bounds__(256)
void dcn_sample(){
    __shared__ float oms[8*OMC];
    int tid = threadIdx.x;
    int pixBase = blockIdx.x * 8;
    for (int i = tid; i < 8*OMC; i += 256)
        oms[i] = g_om[(size_t)pixBase*OMC + i];
    __syncthreads();

    int wid = tid >> 5, lane = tid & 31;
    int g4 = lane >> 3, l8 = lane & 7;
    int m = pixBase + wid;
    int b = m >> 12, rem = m & 4095, y = rem >> 6, x = rem & 63;
    const float* om = oms + wid*OMC;
    __half* colB = g_cols_hi + (size_t)m*KDCN;

    #pragma unroll
    for (int t = 0; t < 9; t++){
        int tyo = t/3 - 1, txo = t - (t/3)*3 - 1;
        #pragma unroll
        for (int gp = 0; gp < 2; gp++){
            int g = gp*4 + g4;
            float dy = om[g*18 + t*2];
            float dx = om[g*18 + t*2 + 1];
            float mk = 1.f / (1.f + __expf(-om[144 + g*9 + t]));  // (2*sig)*0.5
            float py = (float)(y + tyo) + dy;
            float px = (float)(x + txo) + dx;
            float y0f = floorf(py), x0f = floorf(px);
            float wy1 = py - y0f, wx1 = px - x0f;
            float wy0 = 1.f - wy1, wx0 = 1.f - wx1;
            int y0 = (int)y0f, x0 = (int)x0f;
            bool yin0 = ((unsigned)y0 < 64u), yin1 = ((unsigned)(y0+1) < 64u);
            bool xin0 = ((unsigned)x0 < 64u), xin1 = ((unsigned)(x0+1) < 64u);
            float w00 = mk*wy0*wx0, w01 = mk*wy0*wx1;
            float w10 = mk*wy1*wx0, w11 = mk*wy1*wx1;
            const __half* base = g_cat_hi + (size_t)(b << 12)*512 + 256 + g*32 + l8*4;
            int i00 = (y0*64 + x0)*512;
            float a0 = 0.f, a1 = 0.f, a2 = 0.f, a3 = 0.f;
            auto acc4 = [&](int off, float w){
                uint2 u = *(const uint2*)(base + off);
                float2 p0 = __half22float2(*(__half2*)&u.x);
                float2 p1 = __half22float2(*(__half2*)&u.y);
                a0 += w*p0.x; a1 += w*p0.y; a2 += w*p1.x; a3 += w*p1.y;
            };
            if (yin0 && xin0) acc4(i00,             w00);
            if (yin0 && xin1) acc4(i00 + 512,       w01);
            if (yin1 && xin0) acc4(i00 + 32768,     w10);
            if (yin1 && xin1) acc4(i00 + 33280,     w11);
            __half2 h0 = __floats2half2_rn(a0, a1);
            __half2 h1 = __floats2half2_rn(a2, a3);
            uint2 o;
            o.x = *(uint32_t*)&h0;
            o.y = *(uint32_t*)&h1;
            *(uint2*)(colB + t*256 + g*32 + l8*4) = o;
        }
    }
}

// ---------------- launcher -------------------------------------------------------
extern "C" void kernel_launch(void* const* d_in, const int* in_sizes, int n_in,
                              void* d_out, int out_size){
    const float* fine      = (const float*)d_in[0];
    const float* coarse    = (const float*)d_in[1];
    const float* fs_attn_w = (const float*)d_in[2];
    const float* fs_conv_w = (const float*)d_in[3];
    const float* offset_w  = (const float*)d_in[4];
    const float* om_w      = (const float*)d_in[5];
    const float* om_b      = (const float*)d_in[6];
    const float* dcn_w     = (const float*)d_in[7];
    const float* dcn_b     = (const float*)d_in[8];
    float* out = (float*)d_out;
    (void)in_sizes; (void)n_in; (void)out_size;

    const int GSM = 65536;    // 2 stages x (AH,BH) x 16KB
    const int WSM = 98304;    // wcomb: 2 stages x (AH,AL,BH) x 16KB
    cudaFuncSetAttribute(mmagemm<0>, cudaFuncAttributeMaxDynamicSharedMemorySize, GSM);
    cudaFuncSetAttribute(mmagemm<2>, cudaFuncAttributeMaxDynamicSharedMemorySize, GSM);
    cudaFuncSetAttribute(mmagemm<3>, cudaFuncAttributeMaxDynamicSharedMemorySize, GSM);
    cudaFuncSetAttribute(wcomb_attn, cudaFuncAttributeMaxDynamicSharedMemorySize, WSM);

    wprep      <<<9776, 256>>>(fs_conv_w, dcn_w, offset_w, om_w, fine, coarse);
    wcomb_attn <<<76,   256, WSM>>>(fs_attn_w);

    mmagemm<0> <<<dim3(128, 2), 256, GSM>>>(nullptr, nullptr, fine);
    mmagemm<2> <<<dim3(128, 2), 256, GSM>>>(om_b,   nullptr, nullptr);
    dcn_sample <<<2048, 256>>>();
    mmagemm<3> <<<dim3(128, 2), 256, GSM>>>(dcn_b,  out, nullptr);
}